// round 5
// baseline (speedup 1.0000x reference)
#include <cuda_runtime.h>
#include <cuda_bf16.h>
#include <math.h>
#include <stdint.h>

// ============================================================================
// Sizes.  ecc: K=400, SEG=400, K2=800,  K3=1216 (19 chunks of 64)
//         err: K=300, SEG=304, K2=608,  K3=960  (15 chunks of 64)
// Logical GEMM K runs over 3 segments [Xh,Xh,Xl] x [Bh,Bl,Bh]; A stored
// physically as [Xh | Xl] (K2) with seg mapping phys = k3<SEG ? k3 : k3-SEG.
// ============================================================================
#define B_TOT 8192

__device__ __align__(16) __nv_bfloat16 g_A_ecc[B_TOT * 800];
__device__ __align__(16) __nv_bfloat16 g_A_err[B_TOT * 608];
__device__ __align__(16) __nv_bfloat16 g_RT_ecc[256 * 1216];  // [n][k3]
__device__ __align__(16) __nv_bfloat16 g_RT_err[256 * 960];
__device__ float g_Ce[B_TOT * 256];
__device__ float g_Cr[B_TOT * 256];
__device__ float g_bias_part[28 * 256];

// ---------------------------------------------------------------------------
#define MMA16816(d, a, b0_, b1_) \
    asm volatile( \
        "mma.sync.aligned.m16n8k16.row.col.f32.bf16.bf16.f32 " \
        "{%0,%1,%2,%3}, {%4,%5,%6,%7}, {%8,%9}, {%0,%1,%2,%3};" \
        : "+f"((d)[0]), "+f"((d)[1]), "+f"((d)[2]), "+f"((d)[3]) \
        : "r"((a)[0]), "r"((a)[1]), "r"((a)[2]), "r"((a)[3]), \
          "r"(b0_), "r"(b1_))

#define LDSM_X4(r0, r1, r2, r3, addr) \
    asm volatile( \
        "ldmatrix.sync.aligned.m8n8.x4.shared.b16 {%0,%1,%2,%3}, [%4];" \
        : "=r"(r0), "=r"(r1), "=r"(r2), "=r"(r3) : "r"(addr))

__device__ __forceinline__ uint32_t smem_to_u32(const void* p) {
    uint32_t a;
    asm("{ .reg .u64 t; cvta.to.shared.u64 t, %1; cvt.u32.u64 %0, t; }"
        : "=r"(a) : "l"(p));
    return a;
}

// ============================================================================
// K1: convert X fp32 -> bf16 [Xh | Xl].  grid (1024, 2), 256 thr, 8 rows/blk.
// ============================================================================
__global__ void convert_x(const float* __restrict__ ecc,
                          const float* __restrict__ err)
{
    const int graph = blockIdx.y;
    const int K   = graph ? 300 : 400;
    const int SEG = graph ? 304 : 400;
    const int K2  = graph ? 608 : 800;
    const float* src = graph ? err : ecc;
    __nv_bfloat16* dst = graph ? g_A_err : g_A_ecc;
    const int b0 = blockIdx.x * 8;
    const int NU = K2 / 8;

    for (int idx = threadIdx.x; idx < 8 * NU; idx += blockDim.x) {
        const int r = idx / NU, u = idx - r * NU;
        const int b = b0 + r;
        const int k2 = u * 8;
        const bool lo_seg = (k2 >= SEG);
        const int base = k2 - (lo_seg ? SEG : 0);
        unsigned short o[8];
        #pragma unroll
        for (int j = 0; j < 8; j++) {
            const int kq = base + j;
            const float v = (kq < K) ? src[(size_t)b * K + kq] : 0.f;
            __nv_bfloat16 h = __float2bfloat16(v);
            if (lo_seg) h = __float2bfloat16(v - __bfloat162float(h));
            o[j] = __bfloat16_as_ushort(h);
        }
        uint4 w;
        w.x = (uint32_t)o[0] | ((uint32_t)o[1] << 16);
        w.y = (uint32_t)o[2] | ((uint32_t)o[3] << 16);
        w.z = (uint32_t)o[4] | ((uint32_t)o[5] << 16);
        w.w = (uint32_t)o[6] | ((uint32_t)o[7] << 16);
        *(uint4*)(dst + (size_t)b * K2 + k2) = w;
    }
}

// ============================================================================
// K2: fold Conv1d+Cheb+projection into RT[n][k3] (bf16 segs [Bh,Bl,Bh]).
// 28 blocks (16 ecc-u + 12 err-u), 256 threads (h = t). Bias partials too.
// ============================================================================
__global__ __launch_bounds__(256) void precompute(
    const float* __restrict__ wt_ecc, const float* __restrict__ bt_ecc,
    const float* __restrict__ wt_err, const float* __restrict__ bt_err,
    const float* __restrict__ W0_ecc, const float* __restrict__ W1_ecc,
    const float* __restrict__ b_ecc,
    const float* __restrict__ W0_err, const float* __restrict__ W1_err,
    const float* __restrict__ b_err,
    const float* __restrict__ Wp_ecc, const float* __restrict__ bp_ecc,
    const float* __restrict__ Wp_err, const float* __restrict__ bp_err)
{
    const int h   = threadIdx.x;
    const int blk = blockIdx.x;
    const int graph = (blk >= 16);
    const int u     = graph ? blk - 16 : blk;
    const int V     = graph ? 12 : 16;
    const int SEG   = graph ? 304 : 400;
    const int K3    = graph ? 960 : 1216;
    const float* wt = graph ? wt_err : wt_ecc;
    const float* bt = graph ? bt_err : bt_ecc;
    const float* W0 = graph ? W0_err : W0_ecc;
    const float* W1 = graph ? W1_err : W1_ecc;
    const float* bb = graph ? b_err  : b_ecc;
    const float* Wp = graph ? Wp_err : Wp_ecc;
    const float* bp = graph ? bp_err : bp_ecc;
    __nv_bfloat16* RT = graph ? g_RT_err : g_RT_ecc;

    __shared__ __align__(16) float w0s[64 * 28];   // g-major, stride 28
    __shared__ __align__(16) float w1s[64 * 28];   // holds -0.5 * Weff1
    __shared__ float c0s[64];
    __shared__ float part[256];

    // Weff: Conv1d (k=3, SAME, cross-correlation) folded into Cheb weights
    for (int idx = h; idx < 1600; idx += 256) {
        const int tp = idx >> 6, g = idx & 63;
        float s0 = 0.f, s1 = 0.f;
        #pragma unroll 4
        for (int c = 0; c < 32; c++) {
            #pragma unroll
            for (int k = 0; k < 3; k++) {
                const int tt = tp - k + 1;
                if (tt >= 0 && tt < 25) {
                    const float w = wt[c * 3 + k];
                    s0 = fmaf(w, W0[(c * 25 + tt) * 64 + g], s0);
                    s1 = fmaf(w, W1[(c * 25 + tt) * 64 + g], s1);
                }
            }
        }
        w0s[g * 28 + tp] = s0;
        w1s[g * 28 + tp] = -0.5f * s1;
    }
    // c0[g] = sum_c bt[c] * colsum_t (W0 - W1)[c][g] + b[g]
    {
        const int g = h & 63, cb = (h >> 6) * 8;
        float s = 0.f;
        #pragma unroll
        for (int ci = 0; ci < 8; ci++) {
            const int c = cb + ci;
            float a = 0.f;
            #pragma unroll
            for (int tt = 0; tt < 25; tt++)
                a += W0[(c * 25 + tt) * 64 + g] - W1[(c * 25 + tt) * 64 + g];
            s = fmaf(bt[c], a, s);
        }
        part[h] = s;
    }
    __syncthreads();
    if (h < 64)
        c0s[h] = part[h] + part[64 + h] + part[128 + h] + part[192 + h] + bb[h];
    __syncthreads();

    const int up = (u + 1) % V;
    const int um = (u + V - 1) % V;

    float acc[25];
    #pragma unroll
    for (int j = 0; j < 25; j++) acc[j] = 0.f;
    float pbias = (u == 0) ? bp[h] : 0.f;

    for (int g = 0; g < 64; g++) {
        const float wp_u = Wp[(u  * 64 + g) * 256 + h];
        const float wp_s = Wp[(up * 64 + g) * 256 + h] +
                           Wp[(um * 64 + g) * 256 + h];
        pbias = fmaf(c0s[g], wp_u, pbias);
        const float* w0p = w0s + g * 28;
        const float* w1p = w1s + g * 28;
        #pragma unroll
        for (int j = 0; j < 25; j++) {
            acc[j] = fmaf(w0p[j], wp_u, acc[j]);
            acc[j] = fmaf(w1p[j], wp_s, acc[j]);
        }
    }

    __nv_bfloat16* row = RT + (size_t)h * K3;
    #pragma unroll
    for (int j = 0; j < 25; j++) {
        const float v = acc[j];
        const __nv_bfloat16 hi = __float2bfloat16(v);
        const __nv_bfloat16 lo = __float2bfloat16(v - __bfloat162float(hi));
        const int k = u * 25 + j;
        row[k]           = hi;   // seg0: Bh
        row[SEG + k]     = lo;   // seg1: Bl
        row[2 * SEG + k] = hi;   // seg2: Bh
    }
    if (u == 0) {
        const __nv_bfloat16 z = __float2bfloat16(0.f);
        if (graph) {
            for (int k = 300; k < 304; k++) {
                row[k] = z; row[SEG + k] = z; row[2 * SEG + k] = z;
            }
            for (int k = 912; k < 960; k++) row[k] = z;
        } else {
            for (int k = 1200; k < 1216; k++) row[k] = z;
        }
    }
    g_bias_part[blk * 256 + h] = pbias;
}

// ============================================================================
// K3: HMMA GEMM.  grid = (128, 2): x = m-tile*2 + n-tile, y = graph.
// Block tile 128x128, 8 warps at 32x64, m16n8k16 bf16, fp32 accum.
// Smem XOR-swizzled (16B granule ^ (row&7)) -> conflict-free ldmatrix.x4.
// ============================================================================
__global__ __launch_bounds__(256) void gemm_kernel()
{
    __shared__ __align__(16) __nv_bfloat16 As[128 * 64];
    __shared__ __align__(16) __nv_bfloat16 Bs[128 * 64];

    const int tid = threadIdx.x, lane = tid & 31, wid = tid >> 5;
    const int graph  = blockIdx.y;
    const int tile_n = blockIdx.x & 1;
    const int tile_m = blockIdx.x >> 1;
    const int K2  = graph ? 608 : 800;
    const int K3  = graph ? 960 : 1216;
    const int SEG = graph ? 304 : 400;
    const int NC  = K3 / 64;
    const __nv_bfloat16* A  = graph ? g_A_err  : g_A_ecc;
    const __nv_bfloat16* RT = graph ? g_RT_err : g_RT_ecc;
    float* C = graph ? g_Cr : g_Ce;

    const int warp_m = wid & 3, warp_n = wid >> 2;
    const int sub = lane >> 3, i8 = lane & 7;

    float acc[2][8][4];
    #pragma unroll
    for (int mi = 0; mi < 2; mi++)
        #pragma unroll
        for (int ni = 0; ni < 8; ni++)
            #pragma unroll
            for (int q = 0; q < 4; q++) acc[mi][ni][q] = 0.f;

    uint4* As4 = (uint4*)As;
    uint4* Bs4 = (uint4*)Bs;
    const uint32_t As_b = smem_to_u32(As);
    const uint32_t Bs_b = smem_to_u32(Bs);

    for (int kc = 0; kc < NC; kc++) {
        __syncthreads();   // previous chunk's compute done before refill
        // fill A: 128 rows x 8 granules (16B each)
        #pragma unroll
        for (int it = 0; it < 4; it++) {
            const int q = tid + it * 256;
            const int row = q >> 3, kk = q & 7;
            const int k3 = kc * 64 + kk * 8;
            uint4 v = make_uint4(0u, 0u, 0u, 0u);
            if (k3 < 3 * SEG) {
                const int phys = (k3 < SEG) ? k3 : k3 - SEG;
                v = *(const uint4*)(A + (size_t)(tile_m * 128 + row) * K2 + phys);
            }
            As4[row * 8 + (kk ^ (row & 7))] = v;
        }
        // fill B
        #pragma unroll
        for (int it = 0; it < 4; it++) {
            const int q = tid + it * 256;
            const int row = q >> 3, kk = q & 7;
            const uint4 v = *(const uint4*)(RT + (size_t)(tile_n * 128 + row) * K3
                                               + kc * 64 + kk * 8);
            Bs4[row * 8 + (kk ^ (row & 7))] = v;
        }
        __syncthreads();

        #pragma unroll
        for (int ks = 0; ks < 4; ks++) {
            uint32_t a[2][4];
            #pragma unroll
            for (int mi = 0; mi < 2; mi++) {
                const int arow = warp_m * 32 + mi * 16 + i8 + (sub & 1) * 8;
                const int akg  = ks * 2 + (sub >> 1);
                const uint32_t addr =
                    As_b + (uint32_t)(arow * 64 + ((akg ^ (arow & 7)) * 8)) * 2u;
                LDSM_X4(a[mi][0], a[mi][1], a[mi][2], a[mi][3], addr);
            }
            #pragma unroll
            for (int p = 0; p < 4; p++) {
                const int nn  = warp_n * 64 + p * 16 + i8 + (sub >> 1) * 8;
                const int bkg = ks * 2 + (sub & 1);
                const uint32_t addr =
                    Bs_b + (uint32_t)(nn * 64 + ((bkg ^ (nn & 7)) * 8)) * 2u;
                uint32_t b0, b1, b2, b3;
                LDSM_X4(b0, b1, b2, b3, addr);
                MMA16816(acc[0][2 * p],     a[0], b0, b1);
                MMA16816(acc[1][2 * p],     a[1], b0, b1);
                MMA16816(acc[0][2 * p + 1], a[0], b2, b3);
                MMA16816(acc[1][2 * p + 1], a[1], b2, b3);
            }
        }
    }

    // writeback
    const int g = lane >> 2, tg = lane & 3;
    #pragma unroll
    for (int mi = 0; mi < 2; mi++) {
        const int row0 = tile_m * 128 + warp_m * 32 + mi * 16 + g;
        #pragma unroll
        for (int ni = 0; ni < 8; ni++) {
            const int col = tile_n * 128 + warp_n * 64 + ni * 8 + tg * 2;
            *(float2*)(C + (size_t)row0 * 256 + col) =
                make_float2(acc[mi][ni][0], acc[mi][ni][1]);
            *(float2*)(C + (size_t)(row0 + 8) * 256 + col) =
                make_float2(acc[mi][ni][2], acc[mi][ni][3]);
        }
    }
}

// ============================================================================
// K4: epilogue. 512 blocks x 16 rows, 256 threads (col = t).
// ============================================================================
__global__ __launch_bounds__(256) void epilogue(
    const float* __restrict__ ehr,
    const float* __restrict__ Wa, const float* __restrict__ ba,
    const float* __restrict__ We, const float* __restrict__ be,
    const float* __restrict__ Wf2, const float* __restrict__ bf2,
    float* __restrict__ out)
{
    __shared__ float red[16 * 256];
    __shared__ float xs_ehr[16 * 64];
    __shared__ float ehrp[16 * 64];
    __shared__ float attn_s[16];

    const int t = threadIdx.x;
    const int b0 = blockIdx.x * 16;

    float be_sum = 0.f, br_sum = 0.f;
    #pragma unroll
    for (int u = 0; u < 16; u++) be_sum += g_bias_part[u * 256 + t];
    #pragma unroll
    for (int u = 0; u < 12; u++) br_sum += g_bias_part[(16 + u) * 256 + t];

    float e[16], rr[16];
    #pragma unroll
    for (int i = 0; i < 16; i++) {
        e[i]  = g_Ce[(size_t)(b0 + i) * 256 + t] + be_sum;
        rr[i] = g_Cr[(size_t)(b0 + i) * 256 + t] + br_sum;
    }
    for (int idx = t; idx < 16 * 64; idx += 256)
        xs_ehr[idx] = ehr[(size_t)b0 * 64 + idx];
    __syncthreads();

    // ehr MLP: group tg = t/64 handles rows tg*4..+3, col j = t%64
    {
        const int tg = t >> 6, j = t & 63;
        const float bj = be[j];
        #pragma unroll
        for (int q = 0; q < 4; q++) {
            const int r = tg * 4 + q;
            float a = bj;
            #pragma unroll 8
            for (int k = 0; k < 64; k++)
                a = fmaf(xs_ehr[r * 64 + k], We[k * 64 + j], a);
            ehrp[r * 64 + j] = fmaxf(a, 0.f);
        }
    }

    // attention: attn = sigmoid(sum_h tanh(e+r)*Wa[h] + ba)
    const float wa = Wa[t];
    #pragma unroll
    for (int r = 0; r < 16; r++)
        red[r * 256 + t] = tanhf(e[r] + rr[r]) * wa;
    __syncthreads();

    const int wid = t >> 5, lane = t & 31;
    const float ba0 = ba[0], bf0 = bf2[0];
    #pragma unroll
    for (int q = 0; q < 2; q++) {
        const int r = wid * 2 + q;
        float s = 0.f;
        #pragma unroll
        for (int c = 0; c < 8; c++) s += red[r * 256 + c * 32 + lane];
        #pragma unroll
        for (int off = 16; off > 0; off >>= 1)
            s += __shfl_xor_sync(0xffffffffu, s, off);
        if (lane == 0) attn_s[r] = 1.f / (1.f + __expf(-(s + ba0)));
    }
    __syncthreads();

    const float wf  = Wf2[t];
    const float wfe = (t < 64) ? Wf2[256 + t] : 0.f;
    #pragma unroll
    for (int r = 0; r < 16; r++) {
        const float a = attn_s[r];
        float v = fmaxf(a * e[r] + (1.f - a) * rr[r], 0.f) * wf;
        if (t < 64) v = fmaf(ehrp[r * 64 + t], wfe, v);
        red[r * 256 + t] = v;
    }
    __syncthreads();

    #pragma unroll
    for (int q = 0; q < 2; q++) {
        const int r = wid * 2 + q;
        float s = 0.f;
        #pragma unroll
        for (int c = 0; c < 8; c++) s += red[r * 256 + c * 32 + lane];
        #pragma unroll
        for (int off = 16; off > 0; off >>= 1)
            s += __shfl_xor_sync(0xffffffffu, s, off);
        if (lane == 0) out[b0 + r] = 1.f / (1.f + __expf(-(s + bf0)));
    }
}

// ============================================================================
extern "C" void kernel_launch(void* const* d_in, const int* in_sizes, int n_in,
                              void* d_out, int out_size) {
    const float* ecc    = (const float*)d_in[0];
    const float* err    = (const float*)d_in[1];
    const float* ehr    = (const float*)d_in[2];
    const float* wt_ecc = (const float*)d_in[3];
    const float* bt_ecc = (const float*)d_in[4];
    const float* wt_err = (const float*)d_in[5];
    const float* bt_err = (const float*)d_in[6];
    const float* W0_ecc = (const float*)d_in[7];
    const float* W1_ecc = (const float*)d_in[8];
    const float* b_ecc  = (const float*)d_in[9];
    const float* W0_err = (const float*)d_in[10];
    const float* W1_err = (const float*)d_in[11];
    const float* b_err  = (const float*)d_in[12];
    const float* Wp_ecc = (const float*)d_in[13];
    const float* bp_ecc = (const float*)d_in[14];
    const float* Wp_err = (const float*)d_in[15];
    const float* bp_err = (const float*)d_in[16];
    const float* Wa     = (const float*)d_in[17];
    const float* ba     = (const float*)d_in[18];
    const float* We     = (const float*)d_in[19];
    const float* be     = (const float*)d_in[20];
    const float* Wf2    = (const float*)d_in[21];
    const float* bf2    = (const float*)d_in[22];

    dim3 gc(B_TOT / 8, 2);
    convert_x<<<gc, 256>>>(ecc, err);
    precompute<<<28, 256>>>(wt_ecc, bt_ecc, wt_err, bt_err,
                            W0_ecc, W1_ecc, b_ecc, W0_err, W1_err, b_err,
                            Wp_ecc, bp_ecc, Wp_err, bp_err);
    dim3 gg(128, 2);
    gemm_kernel<<<gg, 256>>>();
    epilogue<<<512, 256>>>(ehr, Wa, ba, We, be, Wf2, bf2, (float*)d_out);
}

// round 6
// speedup vs baseline: 1.2325x; 1.2325x over previous
#include <cuda_runtime.h>
#include <cuda_bf16.h>
#include <math.h>
#include <stdint.h>

#define B_TOT 8192

// ============================================================================
// Device globals
// ============================================================================
__device__ __align__(16) __nv_bfloat16 g_Bh_ecc[256 * 448];
__device__ __align__(16) __nv_bfloat16 g_Bl_ecc[256 * 448];
__device__ __align__(16) __nv_bfloat16 g_Bh_err[256 * 320];
__device__ __align__(16) __nv_bfloat16 g_Bl_err[256 * 320];
__device__ float g_bias_part[28 * 256];
__device__ float g_Ce[B_TOT * 256];
__device__ float g_Cr[B_TOT * 256];

// ---------------------------------------------------------------------------
#define MMA16816(d, a, b0_, b1_) \
    asm volatile( \
        "mma.sync.aligned.m16n8k16.row.col.f32.bf16.bf16.f32 " \
        "{%0,%1,%2,%3}, {%4,%5,%6,%7}, {%8,%9}, {%0,%1,%2,%3};" \
        : "+f"((d)[0]), "+f"((d)[1]), "+f"((d)[2]), "+f"((d)[3]) \
        : "r"((a)[0]), "r"((a)[1]), "r"((a)[2]), "r"((a)[3]), \
          "r"(b0_), "r"(b1_))

#define LDSM_X4(r0, r1, r2, r3, addr) \
    asm volatile( \
        "ldmatrix.sync.aligned.m8n8.x4.shared.b16 {%0,%1,%2,%3}, [%4];" \
        : "=r"(r0), "=r"(r1), "=r"(r2), "=r"(r3) : "r"(addr))

#define STS128(r0, r1, r2, r3, addr) \
    asm volatile("st.shared.v4.b32 [%0], {%1, %2, %3, %4};" \
        :: "r"(addr), "r"(r0), "r"(r1), "r"(r2), "r"(r3) : "memory")

#define CP_ASYNC16(dst, src) \
    asm volatile("cp.async.cg.shared.global [%0], [%1], 16;" \
        :: "r"(dst), "l"(src) : "memory")
#define CP_COMMIT() asm volatile("cp.async.commit_group;" ::: "memory")
#define CP_WAIT0()  asm volatile("cp.async.wait_group 0;" ::: "memory")

__device__ __forceinline__ uint32_t smem_to_u32(const void* p) {
    uint32_t a;
    asm("{ .reg .u64 t; cvta.to.shared.u64 t, %1; cvt.u32.u64 %0, t; }"
        : "=r"(a) : "l"(p));
    return a;
}
__device__ __forceinline__ uint32_t pack_hi(float a, float b) {
    return (uint32_t)__bfloat16_as_ushort(__float2bfloat16(a)) |
           ((uint32_t)__bfloat16_as_ushort(__float2bfloat16(b)) << 16);
}
__device__ __forceinline__ uint32_t pack_lo(float a, float b) {
    const float ra = a - __bfloat162float(__float2bfloat16(a));
    const float rb = b - __bfloat162float(__float2bfloat16(b));
    return pack_hi(ra, rb);
}

// ============================================================================
// K1: fold Conv1d+Cheb+projection into B = R^T as bf16 hi/lo [256][KP].
// 28 blocks (16 ecc-u + 12 err-u), 256 threads (h = t). Bias partials too.
// ============================================================================
__global__ __launch_bounds__(256) void precompute(
    const float* __restrict__ wt_ecc, const float* __restrict__ bt_ecc,
    const float* __restrict__ wt_err, const float* __restrict__ bt_err,
    const float* __restrict__ W0_ecc, const float* __restrict__ W1_ecc,
    const float* __restrict__ b_ecc,
    const float* __restrict__ W0_err, const float* __restrict__ W1_err,
    const float* __restrict__ b_err,
    const float* __restrict__ Wp_ecc, const float* __restrict__ bp_ecc,
    const float* __restrict__ Wp_err, const float* __restrict__ bp_err)
{
    const int h   = threadIdx.x;
    const int blk = blockIdx.x;
    const int graph = (blk >= 16);
    const int u     = graph ? blk - 16 : blk;
    const int V     = graph ? 12 : 16;
    const int K     = graph ? 300 : 400;
    const int KP    = graph ? 320 : 448;
    const float* wt = graph ? wt_err : wt_ecc;
    const float* bt = graph ? bt_err : bt_ecc;
    const float* W0 = graph ? W0_err : W0_ecc;
    const float* W1 = graph ? W1_err : W1_ecc;
    const float* bb = graph ? b_err  : b_ecc;
    const float* Wp = graph ? Wp_err : Wp_ecc;
    const float* bp = graph ? bp_err : bp_ecc;
    __nv_bfloat16* Bh = graph ? g_Bh_err : g_Bh_ecc;
    __nv_bfloat16* Bl = graph ? g_Bl_err : g_Bl_ecc;

    __shared__ __align__(16) float w0s[64 * 28];   // g-major, stride 28
    __shared__ __align__(16) float w1s[64 * 28];   // holds -0.5 * Weff1
    __shared__ float c0s[64];
    __shared__ float part[256];

    // Weff: Conv1d (k=3, SAME, cross-correlation) folded into Cheb weights
    for (int idx = h; idx < 1600; idx += 256) {
        const int tp = idx >> 6, g = idx & 63;
        float s0 = 0.f, s1 = 0.f;
        #pragma unroll 4
        for (int c = 0; c < 32; c++) {
            #pragma unroll
            for (int k = 0; k < 3; k++) {
                const int tt = tp - k + 1;
                if (tt >= 0 && tt < 25) {
                    const float w = wt[c * 3 + k];
                    s0 = fmaf(w, W0[(c * 25 + tt) * 64 + g], s0);
                    s1 = fmaf(w, W1[(c * 25 + tt) * 64 + g], s1);
                }
            }
        }
        w0s[g * 28 + tp] = s0;
        w1s[g * 28 + tp] = -0.5f * s1;
    }
    // c0[g] = sum_c bt[c] * colsum_t (W0 - W1)[c][g] + b[g]
    {
        const int g = h & 63, cb = (h >> 6) * 8;
        float s = 0.f;
        #pragma unroll
        for (int ci = 0; ci < 8; ci++) {
            const int c = cb + ci;
            float a = 0.f;
            #pragma unroll
            for (int tt = 0; tt < 25; tt++)
                a += W0[(c * 25 + tt) * 64 + g] - W1[(c * 25 + tt) * 64 + g];
            s = fmaf(bt[c], a, s);
        }
        part[h] = s;
    }
    __syncthreads();
    if (h < 64)
        c0s[h] = part[h] + part[64 + h] + part[128 + h] + part[192 + h] + bb[h];
    __syncthreads();

    const int up = (u + 1) % V;
    const int um = (u + V - 1) % V;

    float acc[25];
    #pragma unroll
    for (int j = 0; j < 25; j++) acc[j] = 0.f;
    float pbias = (u == 0) ? bp[h] : 0.f;

    for (int g = 0; g < 64; g++) {
        const float wp_u = Wp[(u  * 64 + g) * 256 + h];
        const float wp_s = Wp[(up * 64 + g) * 256 + h] +
                           Wp[(um * 64 + g) * 256 + h];
        pbias = fmaf(c0s[g], wp_u, pbias);
        const float* w0p = w0s + g * 28;
        const float* w1p = w1s + g * 28;
        #pragma unroll
        for (int j = 0; j < 25; j++) {
            acc[j] = fmaf(w0p[j], wp_u, acc[j]);
            acc[j] = fmaf(w1p[j], wp_s, acc[j]);
        }
    }

    #pragma unroll
    for (int j = 0; j < 25; j++) {
        const float v = acc[j];
        const __nv_bfloat16 hi = __float2bfloat16(v);
        const int k = u * 25 + j;
        Bh[(size_t)h * KP + k] = hi;
        Bl[(size_t)h * KP + k] = __float2bfloat16(v - __bfloat162float(hi));
    }
    if (u == 0) {
        const __nv_bfloat16 z = __float2bfloat16(0.f);
        for (int k = K; k < KP; k++) {
            Bh[(size_t)h * KP + k] = z;
            Bl[(size_t)h * KP + k] = z;
        }
    }
    g_bias_part[blk * 256 + h] = pbias;
}

// ============================================================================
// K2: pipelined HMMA GEMM with in-kernel fp32->bf16 hi/lo split of A.
// grid (256, 2): x = tile_m*2 + tile_n (128 m-tiles of 64 rows, 2 n-tiles
// of 128 cols), y = graph. 256 threads = 8 warps at 32x32 warp tiles.
// Double-buffered stages: Ah/Al (64x64 bf16) + Bh/Bl (128x64 bf16) = 48KB.
// B via cp.async; A via register prefetch + convert. 3 limb passes
// (Ah*Bh + Ah*Bl + Al*Bh) accumulate into the same fp32 acc. Bias folded in.
// ============================================================================
#define STAGE_SZ 49152
#define AH_OFF   0
#define AL_OFF   8192
#define BH_OFF   16384
#define BL_OFF   32768
#define BIAS_OFF (2 * STAGE_SZ)
#define GEMM_SMEM (BIAS_OFF + 512)

__global__ __launch_bounds__(256) void gemm_kernel(
    const float* __restrict__ ecc, const float* __restrict__ err)
{
    extern __shared__ char dsm[];
    const uint32_t sb = smem_to_u32(dsm);

    const int tid = threadIdx.x, lane = tid & 31, wid = tid >> 5;
    const int graph  = blockIdx.y;
    const int tile_n = blockIdx.x & 1;
    const int tile_m = blockIdx.x >> 1;
    const int K  = graph ? 300 : 400;
    const int KP = graph ? 320 : 448;
    const int NC = graph ? 5 : 7;
    const float* A = graph ? err : ecc;
    const __nv_bfloat16* Bhp = graph ? g_Bh_err : g_Bh_ecc;
    const __nv_bfloat16* Blp = graph ? g_Bl_err : g_Bl_ecc;
    float* C = graph ? g_Cr : g_Ce;

    // bias for this block's 128 columns
    float* bias_s = (float*)(dsm + BIAS_OFF);
    if (tid < 128) {
        const int goff = graph ? 16 : 0;
        const int nu   = graph ? 12 : 16;
        float s = 0.f;
        for (int u = 0; u < nu; u++)
            s += g_bias_part[(goff + u) * 256 + tile_n * 128 + tid];
        bias_s[tid] = s;
    }

    const int warp_m = wid & 1, warp_n = wid >> 1;
    const int sub = lane >> 3, i8 = lane & 7;

    float acc[2][4][4];
    #pragma unroll
    for (int mi = 0; mi < 2; mi++)
        #pragma unroll
        for (int ni = 0; ni < 4; ni++)
            #pragma unroll
            for (int q = 0; q < 4; q++) acc[mi][ni][q] = 0.f;

    // A-load thread mapping: row = tid>>2 (64 rows), quarter q = tid&3
    const int arow_ld = tid >> 2, aq = tid & 3;
    const float* Arow = A + (size_t)(tile_m * 64 + arow_ld) * K;
    float4 va[4];

    // ---- helpers as lambdas ----
    auto ldgA = [&](int c) {
        #pragma unroll
        for (int j = 0; j < 4; j++) {
            const int k = c * 64 + aq * 16 + j * 4;
            va[j] = (k < K) ? *(const float4*)(Arow + k)
                            : make_float4(0.f, 0.f, 0.f, 0.f);
        }
    };
    auto stsA = [&](int c) {
        const uint32_t base = sb + (c & 1) * STAGE_SZ;
        #pragma unroll
        for (int half = 0; half < 2; half++) {
            const float4 p = va[2 * half], q4 = va[2 * half + 1];
            const uint32_t h0 = pack_hi(p.x, p.y), h1 = pack_hi(p.z, p.w);
            const uint32_t h2 = pack_hi(q4.x, q4.y), h3 = pack_hi(q4.z, q4.w);
            const uint32_t l0 = pack_lo(p.x, p.y), l1 = pack_lo(p.z, p.w);
            const uint32_t l2 = pack_lo(q4.x, q4.y), l3 = pack_lo(q4.z, q4.w);
            const int g = aq * 2 + half;
            const uint32_t off =
                (uint32_t)(arow_ld * 8 + (g ^ (arow_ld & 7))) * 16u;
            STS128(h0, h1, h2, h3, base + AH_OFF + off);
            STS128(l0, l1, l2, l3, base + AL_OFF + off);
        }
    };
    auto issueB = [&](int c) {
        const uint32_t base = sb + (c & 1) * STAGE_SZ;
        #pragma unroll
        for (int it = 0; it < 4; it++) {
            const int idx = tid + it * 256;
            const int row = idx >> 3, g = idx & 7;
            const size_t so = (size_t)(tile_n * 128 + row) * KP + c * 64 + g * 8;
            const uint32_t off = (uint32_t)(row * 8 + (g ^ (row & 7))) * 16u;
            CP_ASYNC16(base + BH_OFF + off, (const void*)(Bhp + so));
            CP_ASYNC16(base + BL_OFF + off, (const void*)(Blp + so));
        }
        CP_COMMIT();
    };
    auto compute = [&](int c) {
        const uint32_t base = sb + (c & 1) * STAGE_SZ;
        const int kcnt = min(4, (K - c * 64 + 15) >> 4);
        for (int ks = 0; ks < kcnt; ks++) {
            uint32_t ah[2][4], al[2][4];
            #pragma unroll
            for (int mi = 0; mi < 2; mi++) {
                const int ar = warp_m * 32 + mi * 16 + i8 + (sub & 1) * 8;
                const int akg = ks * 2 + (sub >> 1);
                const uint32_t off =
                    (uint32_t)(ar * 64 + ((akg ^ (ar & 7)) * 8)) * 2u;
                LDSM_X4(ah[mi][0], ah[mi][1], ah[mi][2], ah[mi][3],
                        base + AH_OFF + off);
                LDSM_X4(al[mi][0], al[mi][1], al[mi][2], al[mi][3],
                        base + AL_OFF + off);
            }
            #pragma unroll
            for (int p = 0; p < 2; p++) {
                const int nn = warp_n * 32 + p * 16 + i8 + (sub >> 1) * 8;
                const int bkg = ks * 2 + (sub & 1);
                const uint32_t off =
                    (uint32_t)(nn * 64 + ((bkg ^ (nn & 7)) * 8)) * 2u;
                uint32_t bh0, bh1, bh2, bh3, bl0, bl1, bl2, bl3;
                LDSM_X4(bh0, bh1, bh2, bh3, base + BH_OFF + off);
                LDSM_X4(bl0, bl1, bl2, bl3, base + BL_OFF + off);
                #pragma unroll
                for (int mi = 0; mi < 2; mi++) {
                    MMA16816(acc[mi][2 * p],     ah[mi], bh0, bh1);
                    MMA16816(acc[mi][2 * p],     ah[mi], bl0, bl1);
                    MMA16816(acc[mi][2 * p],     al[mi], bh0, bh1);
                    MMA16816(acc[mi][2 * p + 1], ah[mi], bh2, bh3);
                    MMA16816(acc[mi][2 * p + 1], ah[mi], bl2, bl3);
                    MMA16816(acc[mi][2 * p + 1], al[mi], bh2, bh3);
                }
            }
        }
    };

    // ---- pipeline ----
    issueB(0);
    ldgA(0);
    stsA(0);
    CP_WAIT0();
    __syncthreads();
    if (NC > 1) { ldgA(1); issueB(1); }

    for (int c = 0; c < NC; c++) {
        compute(c);
        __syncthreads();
        if (c + 1 < NC) {
            CP_WAIT0();
            stsA(c + 1);
            if (c + 2 < NC) { ldgA(c + 2); issueB(c + 2); }
            __syncthreads();
        }
    }

    // ---- writeback with bias ----
    const int g8 = lane >> 2, tg = lane & 3;
    #pragma unroll
    for (int mi = 0; mi < 2; mi++) {
        const int row0 = tile_m * 64 + warp_m * 32 + mi * 16 + g8;
        #pragma unroll
        for (int ni = 0; ni < 4; ni++) {
            const int colL = warp_n * 32 + ni * 8 + tg * 2;
            const int col  = tile_n * 128 + colL;
            const float b0 = bias_s[colL], b1 = bias_s[colL + 1];
            *(float2*)(C + (size_t)row0 * 256 + col) =
                make_float2(acc[mi][ni][0] + b0, acc[mi][ni][1] + b1);
            *(float2*)(C + (size_t)(row0 + 8) * 256 + col) =
                make_float2(acc[mi][ni][2] + b0, acc[mi][ni][3] + b1);
        }
    }
}

// ============================================================================
// K3: epilogue, warp-per-row (no block syncs in hot path).
// grid 1024 x 256 threads: warp w handles batch row blockIdx.x*8 + w.
// ============================================================================
__global__ __launch_bounds__(256) void epilogue(
    const float* __restrict__ ehr,
    const float* __restrict__ Wa, const float* __restrict__ ba,
    const float* __restrict__ We, const float* __restrict__ be,
    const float* __restrict__ Wf2, const float* __restrict__ bf2,
    float* __restrict__ out)
{
    __shared__ __align__(16) float We_s[64 * 64];
    __shared__ __align__(16) float ehr_s[8 * 64];

    const int tid = threadIdx.x, w = tid >> 5, l = tid & 31;
    const int b = blockIdx.x * 8 + w;

    #pragma unroll
    for (int i = 0; i < 4; i++)
        ((float4*)We_s)[tid + i * 256] = ((const float4*)We)[tid + i * 256];
    if (tid < 128)
        ((float4*)ehr_s)[tid] =
            ((const float4*)(ehr + (size_t)blockIdx.x * 8 * 64))[tid];
    __syncthreads();

    float e[8], r[8];
    #pragma unroll
    for (int j = 0; j < 8; j++) {
        e[j] = g_Ce[(size_t)b * 256 + l + 32 * j];
        r[j] = g_Cr[(size_t)b * 256 + l + 32 * j];
    }

    // ehr MLP: this lane owns output cols l and l+32
    float o0 = be[l], o1 = be[l + 32];
    #pragma unroll 8
    for (int k = 0; k < 64; k++) {
        const float x = ehr_s[w * 64 + k];
        o0 = fmaf(x, We_s[k * 64 + l], o0);
        o1 = fmaf(x, We_s[k * 64 + l + 32], o1);
    }
    o0 = fmaxf(o0, 0.f);
    o1 = fmaxf(o1, 0.f);

    // attention
    float s = 0.f;
    #pragma unroll
    for (int j = 0; j < 8; j++)
        s = fmaf(tanhf(e[j] + r[j]), Wa[l + 32 * j], s);
    #pragma unroll
    for (int off = 16; off > 0; off >>= 1)
        s += __shfl_xor_sync(0xffffffffu, s, off);
    const float attn = 1.f / (1.f + __expf(-(s + ba[0])));

    // final
    float v = o0 * Wf2[256 + l] + o1 * Wf2[256 + l + 32];
    #pragma unroll
    for (int j = 0; j < 8; j++) {
        const float f = attn * e[j] + (1.f - attn) * r[j];
        v = fmaf(fmaxf(f, 0.f), Wf2[l + 32 * j], v);
    }
    #pragma unroll
    for (int off = 16; off > 0; off >>= 1)
        v += __shfl_xor_sync(0xffffffffu, v, off);
    if (l == 0)
        out[b] = 1.f / (1.f + __expf(-(v + bf2[0])));
}

// ============================================================================
extern "C" void kernel_launch(void* const* d_in, const int* in_sizes, int n_in,
                              void* d_out, int out_size) {
    const float* ecc    = (const float*)d_in[0];
    const float* err    = (const float*)d_in[1];
    const float* ehr    = (const float*)d_in[2];
    const float* wt_ecc = (const float*)d_in[3];
    const float* bt_ecc = (const float*)d_in[4];
    const float* wt_err = (const float*)d_in[5];
    const float* bt_err = (const float*)d_in[6];
    const float* W0_ecc = (const float*)d_in[7];
    const float* W1_ecc = (const float*)d_in[8];
    const float* b_ecc  = (const float*)d_in[9];
    const float* W0_err = (const float*)d_in[10];
    const float* W1_err = (const float*)d_in[11];
    const float* b_err  = (const float*)d_in[12];
    const float* Wp_ecc = (const float*)d_in[13];
    const float* bp_ecc = (const float*)d_in[14];
    const float* Wp_err = (const float*)d_in[15];
    const float* bp_err = (const float*)d_in[16];
    const float* Wa     = (const float*)d_in[17];
    const float* ba     = (const float*)d_in[18];
    const float* We     = (const float*)d_in[19];
    const float* be     = (const float*)d_in[20];
    const float* Wf2    = (const float*)d_in[21];
    const float* bf2    = (const float*)d_in[22];

    cudaFuncSetAttribute(gemm_kernel,
                         cudaFuncAttributeMaxDynamicSharedMemorySize, GEMM_SMEM);

    precompute<<<28, 256>>>(wt_ecc, bt_ecc, wt_err, bt_err,
                            W0_ecc, W1_ecc, b_ecc, W0_err, W1_err, b_err,
                            Wp_ecc, bp_ecc, Wp_err, bp_err);
    dim3 gg(256, 2);
    gemm_kernel<<<gg, 256, GEMM_SMEM>>>(ecc, err);
    epilogue<<<1024, 256>>>(ehr, Wa, ba, We, be, Wf2, bf2, (float*)d_out);
}

// round 7
// speedup vs baseline: 1.5539x; 1.2608x over previous
#include <cuda_runtime.h>
#include <cuda_fp16.h>
#include <math.h>
#include <stdint.h>

#define B_TOT 8192

// ============================================================================
// Device globals
// ============================================================================
__device__ __align__(16) __half g_B_ecc[256 * 448];   // R^T, fp16 hi limb
__device__ __align__(16) __half g_B_err[256 * 320];
__device__ float g_bias_part[28 * 256];
__device__ float g_Ce[B_TOT * 256];
__device__ float g_Cr[B_TOT * 256];

// ---------------------------------------------------------------------------
#define MMA16816(d, a, b0_, b1_) \
    asm volatile( \
        "mma.sync.aligned.m16n8k16.row.col.f32.f16.f16.f32 " \
        "{%0,%1,%2,%3}, {%4,%5,%6,%7}, {%8,%9}, {%0,%1,%2,%3};" \
        : "+f"((d)[0]), "+f"((d)[1]), "+f"((d)[2]), "+f"((d)[3]) \
        : "r"((a)[0]), "r"((a)[1]), "r"((a)[2]), "r"((a)[3]), \
          "r"(b0_), "r"(b1_))

#define LDSM_X4(r0, r1, r2, r3, addr) \
    asm volatile( \
        "ldmatrix.sync.aligned.m8n8.x4.shared.b16 {%0,%1,%2,%3}, [%4];" \
        : "=r"(r0), "=r"(r1), "=r"(r2), "=r"(r3) : "r"(addr))

#define STS128(r0, r1, r2, r3, addr) \
    asm volatile("st.shared.v4.b32 [%0], {%1, %2, %3, %4};" \
        :: "r"(addr), "r"(r0), "r"(r1), "r"(r2), "r"(r3) : "memory")

#define CP_ASYNC16(dst, src) \
    asm volatile("cp.async.cg.shared.global [%0], [%1], 16;" \
        :: "r"(dst), "l"(src) : "memory")
#define CP_COMMIT() asm volatile("cp.async.commit_group;" ::: "memory")
#define CP_WAIT0()  asm volatile("cp.async.wait_group 0;" ::: "memory")

__device__ __forceinline__ uint32_t smem_to_u32(const void* p) {
    uint32_t a;
    asm("{ .reg .u64 t; cvta.to.shared.u64 t, %1; cvt.u32.u64 %0, t; }"
        : "=r"(a) : "l"(p));
    return a;
}
__device__ __forceinline__ uint32_t pack_hi16(float a, float b) {
    return (uint32_t)__half_as_ushort(__float2half(a)) |
           ((uint32_t)__half_as_ushort(__float2half(b)) << 16);
}
__device__ __forceinline__ uint32_t pack_lo16(float a, float b) {
    const float ra = a - __half2float(__float2half(a));
    const float rb = b - __half2float(__float2half(b));
    return pack_hi16(ra, rb);
}

// ============================================================================
// K1: precompute, 140 blocks = (2 graphs) x (V nodes) x (5 tp-groups).
// Each block: (a) Weff rows for its 5 tp values (redundant per-u, but keeps
// 140 blocks busy instead of 28), (b) R rows -> B = R^T fp16, (c) bias
// partials (tpg==0 blocks only).  ecc blocks: 0..79, err blocks: 80..139.
// ============================================================================
__global__ __launch_bounds__(256) void precompute(
    const float* __restrict__ wt_ecc, const float* __restrict__ bt_ecc,
    const float* __restrict__ wt_err, const float* __restrict__ bt_err,
    const float* __restrict__ W0_ecc, const float* __restrict__ W1_ecc,
    const float* __restrict__ b_ecc,
    const float* __restrict__ W0_err, const float* __restrict__ W1_err,
    const float* __restrict__ b_err,
    const float* __restrict__ Wp_ecc, const float* __restrict__ bp_ecc,
    const float* __restrict__ Wp_err, const float* __restrict__ bp_err)
{
    const int blk   = blockIdx.x;
    const int graph = (blk >= 80);
    const int rel   = graph ? blk - 80 : blk;
    const int u     = rel / 5;
    const int tpg   = rel % 5;
    const int V     = graph ? 12 : 16;
    const int K     = graph ? 300 : 400;
    const int KP    = graph ? 320 : 448;
    const float* wt = graph ? wt_err : wt_ecc;
    const float* bt = graph ? bt_err : bt_ecc;
    const float* W0 = graph ? W0_err : W0_ecc;
    const float* W1 = graph ? W1_err : W1_ecc;
    const float* bb = graph ? b_err  : b_ecc;
    const float* Wp = graph ? Wp_err : Wp_ecc;
    const float* bp = graph ? bp_err : bp_ecc;
    __half* B = graph ? g_B_err : g_B_ecc;

    __shared__ float w0s[5 * 64];     // [tp5][g]
    __shared__ float w1s[5 * 64];     // holds -0.5 * Weff1
    __shared__ float c0s[64];
    __shared__ float red0[5 * 256], red1[5 * 256], credp[256];

    const int t = threadIdx.x, g = t & 63, cb = (t >> 6) * 8;

    // ---- phase 1: Weff partials for the 5 tp rows of this block ----
    #pragma unroll
    for (int j = 0; j < 5; j++) {
        const int tp = tpg * 5 + j;
        float s0 = 0.f, s1 = 0.f;
        #pragma unroll
        for (int ci = 0; ci < 8; ci++) {
            const int c = cb + ci;
            #pragma unroll
            for (int k = 0; k < 3; k++) {
                const int tt = tp - k + 1;
                if (tt >= 0 && tt < 25) {
                    const float w = wt[c * 3 + k];
                    s0 = fmaf(w, W0[(c * 25 + tt) * 64 + g], s0);
                    s1 = fmaf(w, W1[(c * 25 + tt) * 64 + g], s1);
                }
            }
        }
        red0[j * 256 + t] = s0;
        red1[j * 256 + t] = s1;
    }
    if (tpg == 0) {
        // c0 partial: sum_c bt[c] * colsum_t (W0 - W1)[c][g]
        float s = 0.f;
        #pragma unroll
        for (int ci = 0; ci < 8; ci++) {
            const int c = cb + ci;
            float a = 0.f;
            #pragma unroll
            for (int tt = 0; tt < 25; tt++)
                a += W0[(c * 25 + tt) * 64 + g] - W1[(c * 25 + tt) * 64 + g];
            s = fmaf(bt[c], a, s);
        }
        credp[t] = s;
    }
    __syncthreads();
    if (t < 64) {
        #pragma unroll
        for (int j = 0; j < 5; j++) {
            w0s[j * 64 + t] = red0[j * 256 + t] + red0[j * 256 + 64 + t] +
                              red0[j * 256 + 128 + t] + red0[j * 256 + 192 + t];
            w1s[j * 64 + t] = -0.5f *
                              (red1[j * 256 + t] + red1[j * 256 + 64 + t] +
                               red1[j * 256 + 128 + t] + red1[j * 256 + 192 + t]);
        }
        if (tpg == 0)
            c0s[t] = credp[t] + credp[64 + t] + credp[128 + t] +
                     credp[192 + t] + bb[t];
    }
    __syncthreads();

    // ---- phase 2: R rows (5) + bias partial ----
    const int h  = t;
    const int up = (u + 1) % V;
    const int um = (u + V - 1) % V;

    float acc[5] = {0.f, 0.f, 0.f, 0.f, 0.f};
    float pbias = (u == 0 && tpg == 0) ? bp[h] : 0.f;

    #pragma unroll 2
    for (int gg = 0; gg < 64; gg++) {
        const float wp_u = Wp[(u  * 64 + gg) * 256 + h];
        const float wp_s = Wp[(up * 64 + gg) * 256 + h] +
                           Wp[(um * 64 + gg) * 256 + h];
        if (tpg == 0) pbias = fmaf(c0s[gg], wp_u, pbias);
        #pragma unroll
        for (int j = 0; j < 5; j++) {
            acc[j] = fmaf(w0s[j * 64 + gg], wp_u, acc[j]);
            acc[j] = fmaf(w1s[j * 64 + gg], wp_s, acc[j]);
        }
    }

    #pragma unroll
    for (int j = 0; j < 5; j++) {
        const int k = u * 25 + tpg * 5 + j;
        B[(size_t)h * KP + k] = __float2half(acc[j]);
    }
    if (u == 0 && tpg == 0) {
        for (int k = K; k < KP; k++)
            B[(size_t)h * KP + k] = __ushort_as_half((unsigned short)0);
        // (tpg==0,u==0) also writes its bias below like other tpg==0 blocks
    }
    if (tpg == 0)
        g_bias_part[((graph ? 16 : 0) + u) * 256 + h] = pbias;
}

// ============================================================================
// K2: pipelined HMMA GEMM, fp16 2-pass (C = Ah*Bh + Al*Bh = A * fp16(B)).
// grid (256, 2): x = tile_m*2 + tile_n, y = graph. 8 warps, 32x32 warp tiles.
// Stages: Ah/Al (64x64 fp16, split in-kernel from fp32 A) + Bh (128x64 fp16)
// = 32KB, double buffered. B via cp.async, A via register prefetch.
// ============================================================================
#define STAGE_SZ 32768
#define AH_OFF   0
#define AL_OFF   8192
#define BH_OFF   16384
#define BIAS_OFF (2 * STAGE_SZ)
#define GEMM_SMEM (BIAS_OFF + 512)

__global__ __launch_bounds__(256) void gemm_kernel(
    const float* __restrict__ ecc, const float* __restrict__ err)
{
    extern __shared__ char dsm[];
    const uint32_t sb = smem_to_u32(dsm);

    const int tid = threadIdx.x, lane = tid & 31, wid = tid >> 5;
    const int graph  = blockIdx.y;
    const int tile_n = blockIdx.x & 1;
    const int tile_m = blockIdx.x >> 1;
    const int K  = graph ? 300 : 400;
    const int KP = graph ? 320 : 448;
    const int NC = graph ? 5 : 7;
    const float* A = graph ? err : ecc;
    const __half* Bp = graph ? g_B_err : g_B_ecc;
    float* C = graph ? g_Cr : g_Ce;

    // bias for this block's 128 columns
    float* bias_s = (float*)(dsm + BIAS_OFF);
    if (tid < 128) {
        const int goff = graph ? 16 : 0;
        const int nu   = graph ? 12 : 16;
        float s = 0.f;
        for (int u = 0; u < nu; u++)
            s += g_bias_part[(goff + u) * 256 + tile_n * 128 + tid];
        bias_s[tid] = s;
    }

    const int warp_m = wid & 1, warp_n = wid >> 1;
    const int sub = lane >> 3, i8 = lane & 7;

    float acc[2][4][4];
    #pragma unroll
    for (int mi = 0; mi < 2; mi++)
        #pragma unroll
        for (int ni = 0; ni < 4; ni++)
            #pragma unroll
            for (int q = 0; q < 4; q++) acc[mi][ni][q] = 0.f;

    // A-load mapping: row = tid>>2 (64 rows), quarter = tid&3 (16 k each)
    const int arow_ld = tid >> 2, aq = tid & 3;
    const float* Arow = A + (size_t)(tile_m * 64 + arow_ld) * K;
    float4 va[4];

    auto ldgA = [&](int c) {
        #pragma unroll
        for (int j = 0; j < 4; j++) {
            const int k = c * 64 + aq * 16 + j * 4;
            va[j] = (k < K) ? *(const float4*)(Arow + k)
                            : make_float4(0.f, 0.f, 0.f, 0.f);
        }
    };
    auto stsA = [&](int c) {
        const uint32_t base = sb + (c & 1) * STAGE_SZ;
        #pragma unroll
        for (int half = 0; half < 2; half++) {
            const float4 p = va[2 * half], q4 = va[2 * half + 1];
            const uint32_t h0 = pack_hi16(p.x, p.y), h1 = pack_hi16(p.z, p.w);
            const uint32_t h2 = pack_hi16(q4.x, q4.y), h3 = pack_hi16(q4.z, q4.w);
            const uint32_t l0 = pack_lo16(p.x, p.y), l1 = pack_lo16(p.z, p.w);
            const uint32_t l2 = pack_lo16(q4.x, q4.y), l3 = pack_lo16(q4.z, q4.w);
            const int g = aq * 2 + half;
            const uint32_t off =
                (uint32_t)(arow_ld * 8 + (g ^ (arow_ld & 7))) * 16u;
            STS128(h0, h1, h2, h3, base + AH_OFF + off);
            STS128(l0, l1, l2, l3, base + AL_OFF + off);
        }
    };
    auto issueB = [&](int c) {
        const uint32_t base = sb + (c & 1) * STAGE_SZ;
        #pragma unroll
        for (int it = 0; it < 4; it++) {
            const int idx = tid + it * 256;
            const int row = idx >> 3, g = idx & 7;
            const size_t so = (size_t)(tile_n * 128 + row) * KP + c * 64 + g * 8;
            const uint32_t off = (uint32_t)(row * 8 + (g ^ (row & 7))) * 16u;
            CP_ASYNC16(base + BH_OFF + off, (const void*)(Bp + so));
        }
        CP_COMMIT();
    };
    auto compute = [&](int c) {
        const uint32_t base = sb + (c & 1) * STAGE_SZ;
        const int kcnt = min(4, (K - c * 64 + 15) >> 4);
        for (int ks = 0; ks < kcnt; ks++) {
            uint32_t ah[2][4], al[2][4];
            #pragma unroll
            for (int mi = 0; mi < 2; mi++) {
                const int ar = warp_m * 32 + mi * 16 + i8 + (sub & 1) * 8;
                const int akg = ks * 2 + (sub >> 1);
                const uint32_t off =
                    (uint32_t)(ar * 64 + ((akg ^ (ar & 7)) * 8)) * 2u;
                LDSM_X4(ah[mi][0], ah[mi][1], ah[mi][2], ah[mi][3],
                        base + AH_OFF + off);
                LDSM_X4(al[mi][0], al[mi][1], al[mi][2], al[mi][3],
                        base + AL_OFF + off);
            }
            #pragma unroll
            for (int p = 0; p < 2; p++) {
                const int nn = warp_n * 32 + p * 16 + i8 + (sub >> 1) * 8;
                const int bkg = ks * 2 + (sub & 1);
                const uint32_t off =
                    (uint32_t)(nn * 64 + ((bkg ^ (nn & 7)) * 8)) * 2u;
                uint32_t b0, b1, b2, b3;
                LDSM_X4(b0, b1, b2, b3, base + BH_OFF + off);
                #pragma unroll
                for (int mi = 0; mi < 2; mi++) {
                    MMA16816(acc[mi][2 * p],     ah[mi], b0, b1);
                    MMA16816(acc[mi][2 * p],     al[mi], b0, b1);
                    MMA16816(acc[mi][2 * p + 1], ah[mi], b2, b3);
                    MMA16816(acc[mi][2 * p + 1], al[mi], b2, b3);
                }
            }
        }
    };

    // ---- pipeline ----
    issueB(0);
    ldgA(0);
    stsA(0);
    CP_WAIT0();
    __syncthreads();
    if (NC > 1) { ldgA(1); issueB(1); }

    for (int c = 0; c < NC; c++) {
        compute(c);
        __syncthreads();
        if (c + 1 < NC) {
            CP_WAIT0();
            stsA(c + 1);
            if (c + 2 < NC) { ldgA(c + 2); issueB(c + 2); }
            __syncthreads();
        }
    }

    // ---- writeback with bias ----
    const int g8 = lane >> 2, tg = lane & 3;
    #pragma unroll
    for (int mi = 0; mi < 2; mi++) {
        const int row0 = tile_m * 64 + warp_m * 32 + mi * 16 + g8;
        #pragma unroll
        for (int ni = 0; ni < 4; ni++) {
            const int colL = warp_n * 32 + ni * 8 + tg * 2;
            const int col  = tile_n * 128 + colL;
            const float b0 = bias_s[colL], b1 = bias_s[colL + 1];
            *(float2*)(C + (size_t)row0 * 256 + col) =
                make_float2(acc[mi][ni][0] + b0, acc[mi][ni][1] + b1);
            *(float2*)(C + (size_t)(row0 + 8) * 256 + col) =
                make_float2(acc[mi][ni][2] + b0, acc[mi][ni][3] + b1);
        }
    }
}

// ============================================================================
// K3: epilogue, warp-per-row. grid 1024 x 256 threads.
// ============================================================================
__global__ __launch_bounds__(256) void epilogue(
    const float* __restrict__ ehr,
    const float* __restrict__ Wa, const float* __restrict__ ba,
    const float* __restrict__ We, const float* __restrict__ be,
    const float* __restrict__ Wf2, const float* __restrict__ bf2,
    float* __restrict__ out)
{
    __shared__ __align__(16) float We_s[64 * 64];
    __shared__ __align__(16) float ehr_s[8 * 64];

    const int tid = threadIdx.x, w = tid >> 5, l = tid & 31;
    const int b = blockIdx.x * 8 + w;

    #pragma unroll
    for (int i = 0; i < 4; i++)
        ((float4*)We_s)[tid + i * 256] = ((const float4*)We)[tid + i * 256];
    if (tid < 128)
        ((float4*)ehr_s)[tid] =
            ((const float4*)(ehr + (size_t)blockIdx.x * 8 * 64))[tid];
    __syncthreads();

    float e[8], r[8];
    #pragma unroll
    for (int j = 0; j < 8; j++) {
        e[j] = g_Ce[(size_t)b * 256 + l + 32 * j];
        r[j] = g_Cr[(size_t)b * 256 + l + 32 * j];
    }

    // ehr MLP: this lane owns output cols l and l+32
    float o0 = be[l], o1 = be[l + 32];
    #pragma unroll 8
    for (int k = 0; k < 64; k++) {
        const float x = ehr_s[w * 64 + k];
        o0 = fmaf(x, We_s[k * 64 + l], o0);
        o1 = fmaf(x, We_s[k * 64 + l + 32], o1);
    }
    o0 = fmaxf(o0, 0.f);
    o1 = fmaxf(o1, 0.f);

    // attention
    float s = 0.f;
    #pragma unroll
    for (int j = 0; j < 8; j++)
        s = fmaf(tanhf(e[j] + r[j]), Wa[l + 32 * j], s);
    #pragma unroll
    for (int off = 16; off > 0; off >>= 1)
        s += __shfl_xor_sync(0xffffffffu, s, off);
    const float attn = 1.f / (1.f + __expf(-(s + ba[0])));

    // final
    float v = o0 * Wf2[256 + l] + o1 * Wf2[256 + l + 32];
    #pragma unroll
    for (int j = 0; j < 8; j++) {
        const float f = attn * e[j] + (1.f - attn) * r[j];
        v = fmaf(fmaxf(f, 0.f), Wf2[l + 32 * j], v);
    }
    #pragma unroll
    for (int off = 16; off > 0; off >>= 1)
        v += __shfl_xor_sync(0xffffffffu, v, off);
    if (l == 0)
        out[b] = 1.f / (1.f + __expf(-(v + bf2[0])));
}

// ============================================================================
extern "C" void kernel_launch(void* const* d_in, const int* in_sizes, int n_in,
                              void* d_out, int out_size) {
    const float* ecc    = (const float*)d_in[0];
    const float* err    = (const float*)d_in[1];
    const float* ehr    = (const float*)d_in[2];
    const float* wt_ecc = (const float*)d_in[3];
    const float* bt_ecc = (const float*)d_in[4];
    const float* wt_err = (const float*)d_in[5];
    const float* bt_err = (const float*)d_in[6];
    const float* W0_ecc = (const float*)d_in[7];
    const float* W1_ecc = (const float*)d_in[8];
    const float* b_ecc  = (const float*)d_in[9];
    const float* W0_err = (const float*)d_in[10];
    const float* W1_err = (const float*)d_in[11];
    const float* b_err  = (const float*)d_in[12];
    const float* Wp_ecc = (const float*)d_in[13];
    const float* bp_ecc = (const float*)d_in[14];
    const float* Wp_err = (const float*)d_in[15];
    const float* bp_err = (const float*)d_in[16];
    const float* Wa     = (const float*)d_in[17];
    const float* ba     = (const float*)d_in[18];
    const float* We     = (const float*)d_in[19];
    const float* be     = (const float*)d_in[20];
    const float* Wf2    = (const float*)d_in[21];
    const float* bf2    = (const float*)d_in[22];

    cudaFuncSetAttribute(gemm_kernel,
                         cudaFuncAttributeMaxDynamicSharedMemorySize, GEMM_SMEM);

    precompute<<<140, 256>>>(wt_ecc, bt_ecc, wt_err, bt_err,
                             W0_ecc, W1_ecc, b_ecc, W0_err, W1_err, b_err,
                             Wp_ecc, bp_ecc, Wp_err, bp_err);
    dim3 gg(256, 2);
    gemm_kernel<<<gg, 256, GEMM_SMEM>>>(ecc, err);
    epilogue<<<1024, 256>>>(ehr, Wa, ba, We, be, Wf2, bf2, (float*)d_out);
}

// round 8
// speedup vs baseline: 2.6197x; 1.6859x over previous
#include <cuda_runtime.h>
#include <cuda_fp16.h>
#include <math.h>
#include <stdint.h>

#define B_TOT 8192

// ============================================================================
// Device globals
// ============================================================================
__device__ float g_w0eff[2 * 25 * 64];   // [graph][tp][g]
__device__ float g_w1eff[2 * 25 * 64];   // holds -0.5 * Weff1
__device__ float g_c0[2 * 64];
__device__ __align__(16) __half g_B_ecc[256 * 448];   // R^T fp16
__device__ __align__(16) __half g_B_err[256 * 320];
__device__ float g_bias_part[28 * 256];
__device__ float g_Ce[B_TOT * 256];
__device__ float g_Cr[B_TOT * 256];

// ---------------------------------------------------------------------------
#define MMA16816(d, a, b0_, b1_) \
    asm volatile( \
        "mma.sync.aligned.m16n8k16.row.col.f32.f16.f16.f32 " \
        "{%0,%1,%2,%3}, {%4,%5,%6,%7}, {%8,%9}, {%0,%1,%2,%3};" \
        : "+f"((d)[0]), "+f"((d)[1]), "+f"((d)[2]), "+f"((d)[3]) \
        : "r"((a)[0]), "r"((a)[1]), "r"((a)[2]), "r"((a)[3]), \
          "r"(b0_), "r"(b1_))

#define LDSM_X4(r0, r1, r2, r3, addr) \
    asm volatile( \
        "ldmatrix.sync.aligned.m8n8.x4.shared.b16 {%0,%1,%2,%3}, [%4];" \
        : "=r"(r0), "=r"(r1), "=r"(r2), "=r"(r3) : "r"(addr))

#define STS128(r0, r1, r2, r3, addr) \
    asm volatile("st.shared.v4.b32 [%0], {%1, %2, %3, %4};" \
        :: "r"(addr), "r"(r0), "r"(r1), "r"(r2), "r"(r3) : "memory")

#define CP_ASYNC16(dst, src) \
    asm volatile("cp.async.cg.shared.global [%0], [%1], 16;" \
        :: "r"(dst), "l"(src) : "memory")
#define CP_COMMIT() asm volatile("cp.async.commit_group;" ::: "memory")
#define CP_WAIT0()  asm volatile("cp.async.wait_group 0;" ::: "memory")

__device__ __forceinline__ uint32_t smem_to_u32(const void* p) {
    uint32_t a;
    asm("{ .reg .u64 t; cvta.to.shared.u64 t, %1; cvt.u32.u64 %0, t; }"
        : "=r"(a) : "l"(p));
    return a;
}
__device__ __forceinline__ uint32_t pack_hi16(float a, float b) {
    return (uint32_t)__half_as_ushort(__float2half(a)) |
           ((uint32_t)__half_as_ushort(__float2half(b)) << 16);
}
__device__ __forceinline__ uint32_t pack_lo16(float a, float b) {
    const float ra = a - __half2float(__float2half(a));
    const float rb = b - __half2float(__float2half(b));
    return pack_hi16(ra, rb);
}

// ============================================================================
// K0: Weff + c0.  grid (2 graphs, 8).  by 0..6: one thread per Weff element
// (96 independent LDGs each -> high MLP). by 7: c0 with smem reduction.
// ============================================================================
__global__ __launch_bounds__(256) void weff_kernel(
    const float* __restrict__ wt_ecc, const float* __restrict__ bt_ecc,
    const float* __restrict__ wt_err, const float* __restrict__ bt_err,
    const float* __restrict__ W0_ecc, const float* __restrict__ W1_ecc,
    const float* __restrict__ b_ecc,
    const float* __restrict__ W0_err, const float* __restrict__ W1_err,
    const float* __restrict__ b_err)
{
    const int graph = blockIdx.x;
    const float* wt = graph ? wt_err : wt_ecc;
    const float* bt = graph ? bt_err : bt_ecc;
    const float* W0 = graph ? W0_err : W0_ecc;
    const float* W1 = graph ? W1_err : W1_ecc;
    const float* bb = graph ? b_err  : b_ecc;
    const int t = threadIdx.x;

    if (blockIdx.y < 7) {
        const int idx = blockIdx.y * 256 + t;
        if (idx >= 1600) return;
        const int tp = idx >> 6, g = idx & 63;
        float s0 = 0.f, s1 = 0.f;
        #pragma unroll 8
        for (int c = 0; c < 32; c++) {
            #pragma unroll
            for (int k = 0; k < 3; k++) {
                const int tt = tp - k + 1;
                if (tt >= 0 && tt < 25) {
                    const float w = wt[c * 3 + k];
                    s0 = fmaf(w, W0[(c * 25 + tt) * 64 + g], s0);
                    s1 = fmaf(w, W1[(c * 25 + tt) * 64 + g], s1);
                }
            }
        }
        g_w0eff[graph * 1600 + idx] = s0;
        g_w1eff[graph * 1600 + idx] = -0.5f * s1;
    } else {
        __shared__ float part[256];
        const int g = t & 63, cb = (t >> 6) * 8;
        float s = 0.f;
        #pragma unroll
        for (int ci = 0; ci < 8; ci++) {
            const int c = cb + ci;
            float a = 0.f;
            #pragma unroll
            for (int tt = 0; tt < 25; tt++)
                a += W0[(c * 25 + tt) * 64 + g] - W1[(c * 25 + tt) * 64 + g];
            s = fmaf(bt[c], a, s);
        }
        part[t] = s;
        __syncthreads();
        if (t < 64)
            g_c0[graph * 64 + g] =
                part[g] + part[64 + g] + part[128 + g] + part[192 + g] + bb[g];
    }
}

// ============================================================================
// K1: R rows.  140 blocks = (2 graphs) x (V nodes) x (5 tp-groups); 256 thr.
// Reads Weff from global (320 floats), does the 64-g loop at unroll 4.
// ecc blocks: 0..79, err blocks: 80..139.
// ============================================================================
__global__ __launch_bounds__(256) void r_kernel(
    const float* __restrict__ Wp_ecc, const float* __restrict__ bp_ecc,
    const float* __restrict__ Wp_err, const float* __restrict__ bp_err)
{
    const int blk   = blockIdx.x;
    const int graph = (blk >= 80);
    const int rel   = graph ? blk - 80 : blk;
    const int u     = rel / 5;
    const int tpg   = rel % 5;
    const int V     = graph ? 12 : 16;
    const int K     = graph ? 300 : 400;
    const int KP    = graph ? 320 : 448;
    const float* Wp = graph ? Wp_err : Wp_ecc;
    const float* bp = graph ? bp_err : bp_ecc;
    __half* B = graph ? g_B_err : g_B_ecc;

    __shared__ float w0s[5 * 64];   // [j][g]
    __shared__ float w1s[5 * 64];
    __shared__ float c0s[64];

    const int t = threadIdx.x;
    if (t < 320) {
        const int src = graph * 1600 + (tpg * 5) * 64 + t;
        w0s[t] = g_w0eff[src];
        w1s[t] = g_w1eff[src];
    } else if (t < 384) {
        c0s[t - 320] = g_c0[graph * 64 + (t - 320)];
    }
    __syncthreads();

    const int h  = t;
    const int up = (u + 1) % V;
    const int um = (u + V - 1) % V;

    float acc[5] = {0.f, 0.f, 0.f, 0.f, 0.f};
    float pbias = (u == 0 && tpg == 0) ? bp[h] : 0.f;

    const float* WpU = Wp + (size_t)(u  * 64) * 256 + h;
    const float* WpP = Wp + (size_t)(up * 64) * 256 + h;
    const float* WpM = Wp + (size_t)(um * 64) * 256 + h;

    #pragma unroll 4
    for (int gg = 0; gg < 64; gg++) {
        const float wp_u = WpU[gg * 256];
        const float wp_s = WpP[gg * 256] + WpM[gg * 256];
        if (tpg == 0) pbias = fmaf(c0s[gg], wp_u, pbias);
        #pragma unroll
        for (int j = 0; j < 5; j++) {
            acc[j] = fmaf(w0s[j * 64 + gg], wp_u, acc[j]);
            acc[j] = fmaf(w1s[j * 64 + gg], wp_s, acc[j]);
        }
    }

    #pragma unroll
    for (int j = 0; j < 5; j++) {
        const int k = u * 25 + tpg * 5 + j;
        B[(size_t)h * KP + k] = __float2half(acc[j]);
    }
    if (u == 0 && tpg == 0) {
        for (int k = K; k < KP; k++)
            B[(size_t)h * KP + k] = __ushort_as_half((unsigned short)0);
        g_bias_part[(graph ? 16 : 0) * 256 + h] = pbias;   // u == 0 partial
    } else if (tpg == 0) {
        g_bias_part[((graph ? 16 : 0) + u) * 256 + h] = pbias;
    }
}

// ============================================================================
// K2: pipelined HMMA GEMM, fp16 2-pass (C = Ah*Bh + Al*Bh = A * fp16(B)).
// grid (256, 2). 8 warps, 32x32 warp tiles, 64x128 block tile.
// ks loop is now compile-time 4 (B zero-padded to KP; A OOB -> 0).
// ============================================================================
#define STAGE_SZ 32768
#define AH_OFF   0
#define AL_OFF   8192
#define BH_OFF   16384
#define BIAS_OFF (2 * STAGE_SZ)
#define GEMM_SMEM (BIAS_OFF + 512)

__global__ __launch_bounds__(256) void gemm_kernel(
    const float* __restrict__ ecc, const float* __restrict__ err)
{
    extern __shared__ char dsm[];
    const uint32_t sb = smem_to_u32(dsm);

    const int tid = threadIdx.x, lane = tid & 31, wid = tid >> 5;
    const int graph  = blockIdx.y;
    const int tile_n = blockIdx.x & 1;
    const int tile_m = blockIdx.x >> 1;
    const int K  = graph ? 300 : 400;
    const int KP = graph ? 320 : 448;
    const int NC = graph ? 5 : 7;
    const float* A = graph ? err : ecc;
    const __half* Bp = graph ? g_B_err : g_B_ecc;
    float* C = graph ? g_Cr : g_Ce;

    float* bias_s = (float*)(dsm + BIAS_OFF);
    if (tid < 128) {
        const int goff = graph ? 16 : 0;
        const int nu   = graph ? 12 : 16;
        float s = 0.f;
        for (int u = 0; u < nu; u++)
            s += g_bias_part[(goff + u) * 256 + tile_n * 128 + tid];
        bias_s[tid] = s;
    }

    const int warp_m = wid & 1, warp_n = wid >> 1;
    const int sub = lane >> 3, i8 = lane & 7;

    float acc[2][4][4];
    #pragma unroll
    for (int mi = 0; mi < 2; mi++)
        #pragma unroll
        for (int ni = 0; ni < 4; ni++)
            #pragma unroll
            for (int q = 0; q < 4; q++) acc[mi][ni][q] = 0.f;

    const int arow_ld = tid >> 2, aq = tid & 3;
    const float* Arow = A + (size_t)(tile_m * 64 + arow_ld) * K;
    float4 va[4];

    auto ldgA = [&](int c) {
        #pragma unroll
        for (int j = 0; j < 4; j++) {
            const int k = c * 64 + aq * 16 + j * 4;
            va[j] = (k < K) ? *(const float4*)(Arow + k)
                            : make_float4(0.f, 0.f, 0.f, 0.f);
        }
    };
    auto stsA = [&](int c) {
        const uint32_t base = sb + (c & 1) * STAGE_SZ;
        #pragma unroll
        for (int half = 0; half < 2; half++) {
            const float4 p = va[2 * half], q4 = va[2 * half + 1];
            const uint32_t h0 = pack_hi16(p.x, p.y), h1 = pack_hi16(p.z, p.w);
            const uint32_t h2 = pack_hi16(q4.x, q4.y), h3 = pack_hi16(q4.z, q4.w);
            const uint32_t l0 = pack_lo16(p.x, p.y), l1 = pack_lo16(p.z, p.w);
            const uint32_t l2 = pack_lo16(q4.x, q4.y), l3 = pack_lo16(q4.z, q4.w);
            const int g = aq * 2 + half;
            const uint32_t off =
                (uint32_t)(arow_ld * 8 + (g ^ (arow_ld & 7))) * 16u;
            STS128(h0, h1, h2, h3, base + AH_OFF + off);
            STS128(l0, l1, l2, l3, base + AL_OFF + off);
        }
    };
    auto issueB = [&](int c) {
        const uint32_t base = sb + (c & 1) * STAGE_SZ;
        #pragma unroll
        for (int it = 0; it < 4; it++) {
            const int idx = tid + it * 256;
            const int row = idx >> 3, g = idx & 7;
            const size_t so = (size_t)(tile_n * 128 + row) * KP + c * 64 + g * 8;
            const uint32_t off = (uint32_t)(row * 8 + (g ^ (row & 7))) * 16u;
            CP_ASYNC16(base + BH_OFF + off, (const void*)(Bp + so));
        }
        CP_COMMIT();
    };
    auto compute = [&](int c) {
        const uint32_t base = sb + (c & 1) * STAGE_SZ;
        #pragma unroll
        for (int ks = 0; ks < 4; ks++) {
            uint32_t ah[2][4], al[2][4];
            #pragma unroll
            for (int mi = 0; mi < 2; mi++) {
                const int ar = warp_m * 32 + mi * 16 + i8 + (sub & 1) * 8;
                const int akg = ks * 2 + (sub >> 1);
                const uint32_t off =
                    (uint32_t)(ar * 64 + ((akg ^ (ar & 7)) * 8)) * 2u;
                LDSM_X4(ah[mi][0], ah[mi][1], ah[mi][2], ah[mi][3],
                        base + AH_OFF + off);
                LDSM_X4(al[mi][0], al[mi][1], al[mi][2], al[mi][3],
                        base + AL_OFF + off);
            }
            #pragma unroll
            for (int p = 0; p < 2; p++) {
                const int nn = warp_n * 32 + p * 16 + i8 + (sub >> 1) * 8;
                const int bkg = ks * 2 + (sub & 1);
                const uint32_t off =
                    (uint32_t)(nn * 64 + ((bkg ^ (nn & 7)) * 8)) * 2u;
                uint32_t b0, b1, b2, b3;
                LDSM_X4(b0, b1, b2, b3, base + BH_OFF + off);
                #pragma unroll
                for (int mi = 0; mi < 2; mi++) {
                    MMA16816(acc[mi][2 * p],     ah[mi], b0, b1);
                    MMA16816(acc[mi][2 * p],     al[mi], b0, b1);
                    MMA16816(acc[mi][2 * p + 1], ah[mi], b2, b3);
                    MMA16816(acc[mi][2 * p + 1], al[mi], b2, b3);
                }
            }
        }
    };

    // ---- pipeline ----
    issueB(0);
    ldgA(0);
    stsA(0);
    CP_WAIT0();
    __syncthreads();
    if (NC > 1) { ldgA(1); issueB(1); }

    for (int c = 0; c < NC; c++) {
        compute(c);
        __syncthreads();
        if (c + 1 < NC) {
            CP_WAIT0();
            stsA(c + 1);
            if (c + 2 < NC) { ldgA(c + 2); issueB(c + 2); }
            __syncthreads();
        }
    }

    // ---- writeback with bias ----
    const int g8 = lane >> 2, tg = lane & 3;
    #pragma unroll
    for (int mi = 0; mi < 2; mi++) {
        const int row0 = tile_m * 64 + warp_m * 32 + mi * 16 + g8;
        #pragma unroll
        for (int ni = 0; ni < 4; ni++) {
            const int colL = warp_n * 32 + ni * 8 + tg * 2;
            const int col  = tile_n * 128 + colL;
            const float b0 = bias_s[colL], b1 = bias_s[colL + 1];
            *(float2*)(C + (size_t)row0 * 256 + col) =
                make_float2(acc[mi][ni][0] + b0, acc[mi][ni][1] + b1);
            *(float2*)(C + (size_t)(row0 + 8) * 256 + col) =
                make_float2(acc[mi][ni][2] + b0, acc[mi][ni][3] + b1);
        }
    }
}

// ============================================================================
// K3: epilogue, warp-per-row. grid 1024 x 256 threads.
// ============================================================================
__global__ __launch_bounds__(256) void epilogue(
    const float* __restrict__ ehr,
    const float* __restrict__ Wa, const float* __restrict__ ba,
    const float* __restrict__ We, const float* __restrict__ be,
    const float* __restrict__ Wf2, const float* __restrict__ bf2,
    float* __restrict__ out)
{
    __shared__ __align__(16) float We_s[64 * 64];
    __shared__ __align__(16) float ehr_s[8 * 64];

    const int tid = threadIdx.x, w = tid >> 5, l = tid & 31;
    const int b = blockIdx.x * 8 + w;

    #pragma unroll
    for (int i = 0; i < 4; i++)
        ((float4*)We_s)[tid + i * 256] = ((const float4*)We)[tid + i * 256];
    if (tid < 128)
        ((float4*)ehr_s)[tid] =
            ((const float4*)(ehr + (size_t)blockIdx.x * 8 * 64))[tid];
    __syncthreads();

    float e[8], r[8];
    #pragma unroll
    for (int j = 0; j < 8; j++) {
        e[j] = g_Ce[(size_t)b * 256 + l + 32 * j];
        r[j] = g_Cr[(size_t)b * 256 + l + 32 * j];
    }

    float o0 = be[l], o1 = be[l + 32];
    #pragma unroll 8
    for (int k = 0; k < 64; k++) {
        const float x = ehr_s[w * 64 + k];
        o0 = fmaf(x, We_s[k * 64 + l], o0);
        o1 = fmaf(x, We_s[k * 64 + l + 32], o1);
    }
    o0 = fmaxf(o0, 0.f);
    o1 = fmaxf(o1, 0.f);

    float s = 0.f;
    #pragma unroll
    for (int j = 0; j < 8; j++)
        s = fmaf(tanhf(e[j] + r[j]), Wa[l + 32 * j], s);
    #pragma unroll
    for (int off = 16; off > 0; off >>= 1)
        s += __shfl_xor_sync(0xffffffffu, s, off);
    const float attn = 1.f / (1.f + __expf(-(s + ba[0])));

    float v = o0 * Wf2[256 + l] + o1 * Wf2[256 + l + 32];
    #pragma unroll
    for (int j = 0; j < 8; j++) {
        const float f = attn * e[j] + (1.f - attn) * r[j];
        v = fmaf(fmaxf(f, 0.f), Wf2[l + 32 * j], v);
    }
    #pragma unroll
    for (int off = 16; off > 0; off >>= 1)
        v += __shfl_xor_sync(0xffffffffu, v, off);
    if (l == 0)
        out[b] = 1.f / (1.f + __expf(-(v + bf2[0])));
}

// ============================================================================
extern "C" void kernel_launch(void* const* d_in, const int* in_sizes, int n_in,
                              void* d_out, int out_size) {
    const float* ecc    = (const float*)d_in[0];
    const float* err    = (const float*)d_in[1];
    const float* ehr    = (const float*)d_in[2];
    const float* wt_ecc = (const float*)d_in[3];
    const float* bt_ecc = (const float*)d_in[4];
    const float* wt_err = (const float*)d_in[5];
    const float* bt_err = (const float*)d_in[6];
    const float* W0_ecc = (const float*)d_in[7];
    const float* W1_ecc = (const float*)d_in[8];
    const float* b_ecc  = (const float*)d_in[9];
    const float* W0_err = (const float*)d_in[10];
    const float* W1_err = (const float*)d_in[11];
    const float* b_err  = (const float*)d_in[12];
    const float* Wp_ecc = (const float*)d_in[13];
    const float* bp_ecc = (const float*)d_in[14];
    const float* Wp_err = (const float*)d_in[15];
    const float* bp_err = (const float*)d_in[16];
    const float* Wa     = (const float*)d_in[17];
    const float* ba     = (const float*)d_in[18];
    const float* We     = (const float*)d_in[19];
    const float* be     = (const float*)d_in[20];
    const float* Wf2    = (const float*)d_in[21];
    const float* bf2    = (const float*)d_in[22];

    cudaFuncSetAttribute(gemm_kernel,
                         cudaFuncAttributeMaxDynamicSharedMemorySize, GEMM_SMEM);

    dim3 gw(2, 8);
    weff_kernel<<<gw, 256>>>(wt_ecc, bt_ecc, wt_err, bt_err,
                             W0_ecc, W1_ecc, b_ecc, W0_err, W1_err, b_err);
    r_kernel<<<140, 256>>>(Wp_ecc, bp_ecc, Wp_err, bp_err);
    dim3 gg(256, 2);
    gemm_kernel<<<gg, 256, GEMM_SMEM>>>(ecc, err);
    epilogue<<<1024, 256>>>(ehr, Wa, ba, We, be, Wf2, bf2, (float*)d_out);
}

// round 9
// speedup vs baseline: 2.8966x; 1.1057x over previous
#include <cuda_runtime.h>
#include <cuda_fp16.h>
#include <math.h>
#include <stdint.h>

#define B_TOT 8192

// ============================================================================
// Device globals
// ============================================================================
__device__ float g_w0eff[2 * 25 * 64];   // [graph][tp][g]
__device__ float g_w1eff[2 * 25 * 64];   // holds -0.5 * Weff1
__device__ float g_c0[2 * 64];
__device__ __align__(16) __half g_B_ecc[256 * 448];   // R^T fp16
__device__ __align__(16) __half g_B_err[256 * 320];
__device__ float g_bias_part[28 * 256];
__device__ float g_Ce[B_TOT * 256];
__device__ float g_Cr[B_TOT * 256];

// ---------------------------------------------------------------------------
#define MMA16816(d, a, b0_, b1_) \
    asm volatile( \
        "mma.sync.aligned.m16n8k16.row.col.f32.f16.f16.f32 " \
        "{%0,%1,%2,%3}, {%4,%5,%6,%7}, {%8,%9}, {%0,%1,%2,%3};" \
        : "+f"((d)[0]), "+f"((d)[1]), "+f"((d)[2]), "+f"((d)[3]) \
        : "r"((a)[0]), "r"((a)[1]), "r"((a)[2]), "r"((a)[3]), \
          "r"(b0_), "r"(b1_))

#define LDSM_X4(r0, r1, r2, r3, addr) \
    asm volatile( \
        "ldmatrix.sync.aligned.m8n8.x4.shared.b16 {%0,%1,%2,%3}, [%4];" \
        : "=r"(r0), "=r"(r1), "=r"(r2), "=r"(r3) : "r"(addr))

#define STS128(r0, r1, r2, r3, addr) \
    asm volatile("st.shared.v4.b32 [%0], {%1, %2, %3, %4};" \
        :: "r"(addr), "r"(r0), "r"(r1), "r"(r2), "r"(r3) : "memory")

#define CP_ASYNC16(dst, src) \
    asm volatile("cp.async.cg.shared.global [%0], [%1], 16;" \
        :: "r"(dst), "l"(src) : "memory")
#define CP_COMMIT() asm volatile("cp.async.commit_group;" ::: "memory")
#define CP_WAIT0()  asm volatile("cp.async.wait_group 0;" ::: "memory")

__device__ __forceinline__ uint32_t smem_to_u32(const void* p) {
    uint32_t a;
    asm("{ .reg .u64 t; cvta.to.shared.u64 t, %1; cvt.u32.u64 %0, t; }"
        : "=r"(a) : "l"(p));
    return a;
}
__device__ __forceinline__ uint32_t pack_hi16(float a, float b) {
    return (uint32_t)__half_as_ushort(__float2half(a)) |
           ((uint32_t)__half_as_ushort(__float2half(b)) << 16);
}
__device__ __forceinline__ float tanh_fast(float x) {
    float y;
    asm("tanh.approx.f32 %0, %1;" : "=f"(y) : "f"(x));
    return y;
}

// ============================================================================
// K0: Weff + c0.  grid (2 graphs, 8).  by 0..6: one thread per Weff element.
// by 7: c0 with smem reduction.
// ============================================================================
__global__ __launch_bounds__(256) void weff_kernel(
    const float* __restrict__ wt_ecc, const float* __restrict__ bt_ecc,
    const float* __restrict__ wt_err, const float* __restrict__ bt_err,
    const float* __restrict__ W0_ecc, const float* __restrict__ W1_ecc,
    const float* __restrict__ b_ecc,
    const float* __restrict__ W0_err, const float* __restrict__ W1_err,
    const float* __restrict__ b_err)
{
    const int graph = blockIdx.x;
    const float* wt = graph ? wt_err : wt_ecc;
    const float* bt = graph ? bt_err : bt_ecc;
    const float* W0 = graph ? W0_err : W0_ecc;
    const float* W1 = graph ? W1_err : W1_ecc;
    const float* bb = graph ? b_err  : b_ecc;
    const int t = threadIdx.x;

    if (blockIdx.y < 7) {
        const int idx = blockIdx.y * 256 + t;
        if (idx >= 1600) return;
        const int tp = idx >> 6, g = idx & 63;
        float s0 = 0.f, s1 = 0.f;
        #pragma unroll 8
        for (int c = 0; c < 32; c++) {
            #pragma unroll
            for (int k = 0; k < 3; k++) {
                const int tt = tp - k + 1;
                if (tt >= 0 && tt < 25) {
                    const float w = wt[c * 3 + k];
                    s0 = fmaf(w, W0[(c * 25 + tt) * 64 + g], s0);
                    s1 = fmaf(w, W1[(c * 25 + tt) * 64 + g], s1);
                }
            }
        }
        g_w0eff[graph * 1600 + idx] = s0;
        g_w1eff[graph * 1600 + idx] = -0.5f * s1;
    } else {
        __shared__ float part[256];
        const int g = t & 63, cb = (t >> 6) * 8;
        float s = 0.f;
        #pragma unroll
        for (int ci = 0; ci < 8; ci++) {
            const int c = cb + ci;
            float a = 0.f;
            #pragma unroll
            for (int tt = 0; tt < 25; tt++)
                a += W0[(c * 25 + tt) * 64 + g] - W1[(c * 25 + tt) * 64 + g];
            s = fmaf(bt[c], a, s);
        }
        part[t] = s;
        __syncthreads();
        if (t < 64)
            g_c0[graph * 64 + g] =
                part[g] + part[64 + g] + part[128 + g] + part[192 + g] + bb[g];
    }
}

// ============================================================================
// K1: R rows.  140 blocks = (2 graphs) x (V nodes) x (5 tp-groups); 256 thr.
// FIX vs round 8: the 320-element Weff stage and the 64-element c0 stage are
// now loaded with a strided loop / t<64 guard (previously elements 256..319
// and ALL of c0s were never written by a 256-thread block -> stale smem).
// ============================================================================
__global__ __launch_bounds__(256) void r_kernel(
    const float* __restrict__ Wp_ecc, const float* __restrict__ bp_ecc,
    const float* __restrict__ Wp_err, const float* __restrict__ bp_err)
{
    const int blk   = blockIdx.x;
    const int graph = (blk >= 80);
    const int rel   = graph ? blk - 80 : blk;
    const int u     = rel / 5;
    const int tpg   = rel % 5;
    const int V     = graph ? 12 : 16;
    const int K     = graph ? 300 : 400;
    const int KP    = graph ? 320 : 448;
    const float* Wp = graph ? Wp_err : Wp_ecc;
    const float* bp = graph ? bp_err : bp_ecc;
    __half* B = graph ? g_B_err : g_B_ecc;

    __shared__ float w0s[5 * 64];   // [j][g]
    __shared__ float w1s[5 * 64];
    __shared__ float c0s[64];

    const int t = threadIdx.x;
    for (int i = t; i < 320; i += 256) {
        const int src = graph * 1600 + tpg * 320 + i;
        w0s[i] = g_w0eff[src];
        w1s[i] = g_w1eff[src];
    }
    if (t < 64) c0s[t] = g_c0[graph * 64 + t];
    __syncthreads();

    const int h  = t;
    const int up = (u + 1) % V;
    const int um = (u + V - 1) % V;

    float acc[5] = {0.f, 0.f, 0.f, 0.f, 0.f};
    float pbias = (u == 0 && tpg == 0) ? bp[h] : 0.f;

    const float* WpU = Wp + (size_t)(u  * 64) * 256 + h;
    const float* WpP = Wp + (size_t)(up * 64) * 256 + h;
    const float* WpM = Wp + (size_t)(um * 64) * 256 + h;

    #pragma unroll 4
    for (int gg = 0; gg < 64; gg++) {
        const float wp_u = WpU[gg * 256];
        const float wp_s = WpP[gg * 256] + WpM[gg * 256];
        if (tpg == 0) pbias = fmaf(c0s[gg], wp_u, pbias);
        #pragma unroll
        for (int j = 0; j < 5; j++) {
            acc[j] = fmaf(w0s[j * 64 + gg], wp_u, acc[j]);
            acc[j] = fmaf(w1s[j * 64 + gg], wp_s, acc[j]);
        }
    }

    #pragma unroll
    for (int j = 0; j < 5; j++) {
        const int k = u * 25 + tpg * 5 + j;
        B[(size_t)h * KP + k] = __float2half(acc[j]);
    }
    if (u == 0 && tpg == 0) {
        for (int k = K; k < KP; k++)
            B[(size_t)h * KP + k] = __ushort_as_half((unsigned short)0);
    }
    if (tpg == 0)
        g_bias_part[((graph ? 16 : 0) + u) * 256 + h] = pbias;
}

// ============================================================================
// K2: pipelined HMMA GEMM, SINGLE-pass fp16 (C = fp16(A) * fp16(B)).
// Empirical basis: exact-A x fp16(B) measured rel_err 2.3e-7 (round 7); the
// A-rounding term is the same order, so total stays ~5e-7 << 1e-3.
// grid (256, 2). 8 warps, 32x32 warp tiles, 64x128 block tile, ks unrolled 4.
// ============================================================================
#define STAGE_SZ 24576
#define AH_OFF   0
#define BH_OFF   8192
#define BIAS_OFF (2 * STAGE_SZ)
#define GEMM_SMEM (BIAS_OFF + 512)

__global__ __launch_bounds__(256) void gemm_kernel(
    const float* __restrict__ ecc, const float* __restrict__ err)
{
    extern __shared__ char dsm[];
    const uint32_t sb = smem_to_u32(dsm);

    const int tid = threadIdx.x, lane = tid & 31, wid = tid >> 5;
    const int graph  = blockIdx.y;
    const int tile_n = blockIdx.x & 1;
    const int tile_m = blockIdx.x >> 1;
    const int K  = graph ? 300 : 400;
    const int KP = graph ? 320 : 448;
    const int NC = graph ? 5 : 7;
    const float* A = graph ? err : ecc;
    const __half* Bp = graph ? g_B_err : g_B_ecc;
    float* C = graph ? g_Cr : g_Ce;

    float* bias_s = (float*)(dsm + BIAS_OFF);
    if (tid < 128) {
        const int goff = graph ? 16 : 0;
        const int nu   = graph ? 12 : 16;
        float s = 0.f;
        for (int u = 0; u < nu; u++)
            s += g_bias_part[(goff + u) * 256 + tile_n * 128 + tid];
        bias_s[tid] = s;
    }

    const int warp_m = wid & 1, warp_n = wid >> 1;
    const int sub = lane >> 3, i8 = lane & 7;

    float acc[2][4][4];
    #pragma unroll
    for (int mi = 0; mi < 2; mi++)
        #pragma unroll
        for (int ni = 0; ni < 4; ni++)
            #pragma unroll
            for (int q = 0; q < 4; q++) acc[mi][ni][q] = 0.f;

    const int arow_ld = tid >> 2, aq = tid & 3;
    const float* Arow = A + (size_t)(tile_m * 64 + arow_ld) * K;
    float4 va[4];

    auto ldgA = [&](int c) {
        #pragma unroll
        for (int j = 0; j < 4; j++) {
            const int k = c * 64 + aq * 16 + j * 4;
            va[j] = (k < K) ? *(const float4*)(Arow + k)
                            : make_float4(0.f, 0.f, 0.f, 0.f);
        }
    };
    auto stsA = [&](int c) {
        const uint32_t base = sb + (c & 1) * STAGE_SZ;
        #pragma unroll
        for (int half = 0; half < 2; half++) {
            const float4 p = va[2 * half], q4 = va[2 * half + 1];
            const uint32_t h0 = pack_hi16(p.x, p.y), h1 = pack_hi16(p.z, p.w);
            const uint32_t h2 = pack_hi16(q4.x, q4.y), h3 = pack_hi16(q4.z, q4.w);
            const int g = aq * 2 + half;
            const uint32_t off =
                (uint32_t)(arow_ld * 8 + (g ^ (arow_ld & 7))) * 16u;
            STS128(h0, h1, h2, h3, base + AH_OFF + off);
        }
    };
    auto issueB = [&](int c) {
        const uint32_t base = sb + (c & 1) * STAGE_SZ;
        #pragma unroll
        for (int it = 0; it < 4; it++) {
            const int idx = tid + it * 256;
            const int row = idx >> 3, g = idx & 7;
            const size_t so = (size_t)(tile_n * 128 + row) * KP + c * 64 + g * 8;
            const uint32_t off = (uint32_t)(row * 8 + (g ^ (row & 7))) * 16u;
            CP_ASYNC16(base + BH_OFF + off, (const void*)(Bp + so));
        }
        CP_COMMIT();
    };
    auto compute = [&](int c) {
        const uint32_t base = sb + (c & 1) * STAGE_SZ;
        #pragma unroll
        for (int ks = 0; ks < 4; ks++) {
            uint32_t ah[2][4];
            #pragma unroll
            for (int mi = 0; mi < 2; mi++) {
                const int ar = warp_m * 32 + mi * 16 + i8 + (sub & 1) * 8;
                const int akg = ks * 2 + (sub >> 1);
                const uint32_t off =
                    (uint32_t)(ar * 64 + ((akg ^ (ar & 7)) * 8)) * 2u;
                LDSM_X4(ah[mi][0], ah[mi][1], ah[mi][2], ah[mi][3],
                        base + AH_OFF + off);
            }
            #pragma unroll
            for (int p = 0; p < 2; p++) {
                const int nn = warp_n * 32 + p * 16 + i8 + (sub >> 1) * 8;
                const int bkg = ks * 2 + (sub & 1);
                const uint32_t off =
                    (uint32_t)(nn * 64 + ((bkg ^ (nn & 7)) * 8)) * 2u;
                uint32_t b0, b1, b2, b3;
                LDSM_X4(b0, b1, b2, b3, base + BH_OFF + off);
                #pragma unroll
                for (int mi = 0; mi < 2; mi++) {
                    MMA16816(acc[mi][2 * p],     ah[mi], b0, b1);
                    MMA16816(acc[mi][2 * p + 1], ah[mi], b2, b3);
                }
            }
        }
    };

    // ---- pipeline ----
    issueB(0);
    ldgA(0);
    stsA(0);
    CP_WAIT0();
    __syncthreads();
    if (NC > 1) { ldgA(1); issueB(1); }

    for (int c = 0; c < NC; c++) {
        compute(c);
        __syncthreads();
        if (c + 1 < NC) {
            CP_WAIT0();
            stsA(c + 1);
            if (c + 2 < NC) { ldgA(c + 2); issueB(c + 2); }
            __syncthreads();
        }
    }

    // ---- writeback with bias ----
    const int g8 = lane >> 2, tg = lane & 3;
    #pragma unroll
    for (int mi = 0; mi < 2; mi++) {
        const int row0 = tile_m * 64 + warp_m * 32 + mi * 16 + g8;
        #pragma unroll
        for (int ni = 0; ni < 4; ni++) {
            const int colL = warp_n * 32 + ni * 8 + tg * 2;
            const int col  = tile_n * 128 + colL;
            const float b0 = bias_s[colL], b1 = bias_s[colL + 1];
            *(float2*)(C + (size_t)row0 * 256 + col) =
                make_float2(acc[mi][ni][0] + b0, acc[mi][ni][1] + b1);
            *(float2*)(C + (size_t)(row0 + 8) * 256 + col) =
                make_float2(acc[mi][ni][2] + b0, acc[mi][ni][3] + b1);
        }
    }
}

// ============================================================================
// K3: epilogue, warp-per-row. grid 1024 x 256 threads.
// Inner tanh -> tanh.approx (error damped by Wa ~0.02 before the sigmoid);
// final sigmoids stay exact __expf.
// ============================================================================
__global__ __launch_bounds__(256) void epilogue(
    const float* __restrict__ ehr,
    const float* __restrict__ Wa, const float* __restrict__ ba,
    const float* __restrict__ We, const float* __restrict__ be,
    const float* __restrict__ Wf2, const float* __restrict__ bf2,
    float* __restrict__ out)
{
    __shared__ __align__(16) float We_s[64 * 64];
    __shared__ __align__(16) float ehr_s[8 * 64];

    const int tid = threadIdx.x, w = tid >> 5, l = tid & 31;
    const int b = blockIdx.x * 8 + w;

    float e[8], r[8];
    #pragma unroll
    for (int j = 0; j < 8; j++) {
        e[j] = g_Ce[(size_t)b * 256 + l + 32 * j];
        r[j] = g_Cr[(size_t)b * 256 + l + 32 * j];
    }

    #pragma unroll
    for (int i = 0; i < 4; i++)
        ((float4*)We_s)[tid + i * 256] = ((const float4*)We)[tid + i * 256];
    if (tid < 128)
        ((float4*)ehr_s)[tid] =
            ((const float4*)(ehr + (size_t)blockIdx.x * 8 * 64))[tid];
    __syncthreads();

    float o0 = be[l], o1 = be[l + 32];
    #pragma unroll 8
    for (int k = 0; k < 64; k++) {
        const float x = ehr_s[w * 64 + k];
        o0 = fmaf(x, We_s[k * 64 + l], o0);
        o1 = fmaf(x, We_s[k * 64 + l + 32], o1);
    }
    o0 = fmaxf(o0, 0.f);
    o1 = fmaxf(o1, 0.f);

    float s = 0.f;
    #pragma unroll
    for (int j = 0; j < 8; j++)
        s = fmaf(tanh_fast(e[j] + r[j]), Wa[l + 32 * j], s);
    #pragma unroll
    for (int off = 16; off > 0; off >>= 1)
        s += __shfl_xor_sync(0xffffffffu, s, off);
    const float attn = 1.f / (1.f + __expf(-(s + ba[0])));

    float v = o0 * Wf2[256 + l] + o1 * Wf2[256 + l + 32];
    #pragma unroll
    for (int j = 0; j < 8; j++) {
        const float f = attn * e[j] + (1.f - attn) * r[j];
        v = fmaf(fmaxf(f, 0.f), Wf2[l + 32 * j], v);
    }
    #pragma unroll
    for (int off = 16; off > 0; off >>= 1)
        v += __shfl_xor_sync(0xffffffffu, v, off);
    if (l == 0)
        out[b] = 1.f / (1.f + __expf(-(v + bf2[0])));
}

// ============================================================================
extern "C" void kernel_launch(void* const* d_in, const int* in_sizes, int n_in,
                              void* d_out, int out_size) {
    const float* ecc    = (const float*)d_in[0];
    const float* err    = (const float*)d_in[1];
    const float* ehr    = (const float*)d_in[2];
    const float* wt_ecc = (const float*)d_in[3];
    const float* bt_ecc = (const float*)d_in[4];
    const float* wt_err = (const float*)d_in[5];
    const float* bt_err = (const float*)d_in[6];
    const float* W0_ecc = (const float*)d_in[7];
    const float* W1_ecc = (const float*)d_in[8];
    const float* b_ecc  = (const float*)d_in[9];
    const float* W0_err = (const float*)d_in[10];
    const float* W1_err = (const float*)d_in[11];
    const float* b_err  = (const float*)d_in[12];
    const float* Wp_ecc = (const float*)d_in[13];
    const float* bp_ecc = (const float*)d_in[14];
    const float* Wp_err = (const float*)d_in[15];
    const float* bp_err = (const float*)d_in[16];
    const float* Wa     = (const float*)d_in[17];
    const float* ba     = (const float*)d_in[18];
    const float* We     = (const float*)d_in[19];
    const float* be     = (const float*)d_in[20];
    const float* Wf2    = (const float*)d_in[21];
    const float* bf2    = (const float*)d_in[22];

    cudaFuncSetAttribute(gemm_kernel,
                         cudaFuncAttributeMaxDynamicSharedMemorySize, GEMM_SMEM);

    dim3 gw(2, 8);
    weff_kernel<<<gw, 256>>>(wt_ecc, bt_ecc, wt_err, bt_err,
                             W0_ecc, W1_ecc, b_ecc, W0_err, W1_err, b_err);
    r_kernel<<<140, 256>>>(Wp_ecc, bp_ecc, Wp_err, bp_err);
    dim3 gg(256, 2);
    gemm_kernel<<<gg, 256, GEMM_SMEM>>>(ecc, err);
    epilogue<<<1024, 256>>>(ehr, Wa, ba, We, be, Wf2, bf2, (float*)d_out);
}

// round 10
// speedup vs baseline: 2.9348x; 1.0132x over previous
#include <cuda_runtime.h>
#include <cuda_fp16.h>
#include <math.h>
#include <stdint.h>

#define B_TOT 8192

// ============================================================================
// Device globals
// ============================================================================
__device__ float g_w0eff[2 * 25 * 64];   // [graph][tp][g]
__device__ float g_w1eff[2 * 25 * 64];   // holds -0.5 * Weff1
__device__ float g_c0[2 * 64];
__device__ __align__(16) __half g_B_ecc[256 * 448];   // R^T fp16
__device__ __align__(16) __half g_B_err[256 * 320];
__device__ float g_bias_part[28 * 256];

// ---------------------------------------------------------------------------
#define MMA16816(d, a, b0_, b1_) \
    asm volatile( \
        "mma.sync.aligned.m16n8k16.row.col.f32.f16.f16.f32 " \
        "{%0,%1,%2,%3}, {%4,%5,%6,%7}, {%8,%9}, {%0,%1,%2,%3};" \
        : "+f"((d)[0]), "+f"((d)[1]), "+f"((d)[2]), "+f"((d)[3]) \
        : "r"((a)[0]), "r"((a)[1]), "r"((a)[2]), "r"((a)[3]), \
          "r"(b0_), "r"(b1_))

#define LDSM_X4(r0, r1, r2, r3, addr) \
    asm volatile( \
        "ldmatrix.sync.aligned.m8n8.x4.shared.b16 {%0,%1,%2,%3}, [%4];" \
        : "=r"(r0), "=r"(r1), "=r"(r2), "=r"(r3) : "r"(addr))

#define STS128(r0, r1, r2, r3, addr) \
    asm volatile("st.shared.v4.b32 [%0], {%1, %2, %3, %4};" \
        :: "r"(addr), "r"(r0), "r"(r1), "r"(r2), "r"(r3) : "memory")

#define CP_ASYNC16(dst, src) \
    asm volatile("cp.async.cg.shared.global [%0], [%1], 16;" \
        :: "r"(dst), "l"(src) : "memory")
#define CP_COMMIT() asm volatile("cp.async.commit_group;" ::: "memory")
#define CP_WAIT0()  asm volatile("cp.async.wait_group 0;" ::: "memory")

__device__ __forceinline__ uint32_t smem_to_u32(const void* p) {
    uint32_t a;
    asm("{ .reg .u64 t; cvta.to.shared.u64 t, %1; cvt.u32.u64 %0, t; }"
        : "=r"(a) : "l"(p));
    return a;
}
__device__ __forceinline__ uint32_t pack_hi16(float a, float b) {
    return (uint32_t)__half_as_ushort(__float2half(a)) |
           ((uint32_t)__half_as_ushort(__float2half(b)) << 16);
}
__device__ __forceinline__ float tanh_fast(float x) {
    float y;
    asm("tanh.approx.f32 %0, %1;" : "=f"(y) : "f"(x));
    return y;
}

// ============================================================================
// K0: Weff + c0.  grid (2 graphs, 26).
// y = 0..24: one Weff row tp per block; 256 thr = (4 channel-chunks) x (64 g),
//            smem 4-way reduce. y = 25: c0.
// ============================================================================
__global__ __launch_bounds__(256) void weff_kernel(
    const float* __restrict__ wt_ecc, const float* __restrict__ bt_ecc,
    const float* __restrict__ wt_err, const float* __restrict__ bt_err,
    const float* __restrict__ W0_ecc, const float* __restrict__ W1_ecc,
    const float* __restrict__ b_ecc,
    const float* __restrict__ W0_err, const float* __restrict__ W1_err,
    const float* __restrict__ b_err)
{
    const int graph = blockIdx.x;
    const float* wt = graph ? wt_err : wt_ecc;
    const float* bt = graph ? bt_err : bt_ecc;
    const float* W0 = graph ? W0_err : W0_ecc;
    const float* W1 = graph ? W1_err : W1_ecc;
    const float* bb = graph ? b_err  : b_ecc;
    const int t = threadIdx.x, g = t & 63, cb = (t >> 6) * 8;

    __shared__ float p0[256], p1[256];

    if (blockIdx.y < 25) {
        const int tp = blockIdx.y;
        float s0 = 0.f, s1 = 0.f;
        #pragma unroll
        for (int ci = 0; ci < 8; ci++) {
            const int c = cb + ci;
            #pragma unroll
            for (int k = 0; k < 3; k++) {
                const int tt = tp - k + 1;
                if (tt >= 0 && tt < 25) {
                    const float w = wt[c * 3 + k];
                    s0 = fmaf(w, W0[(c * 25 + tt) * 64 + g], s0);
                    s1 = fmaf(w, W1[(c * 25 + tt) * 64 + g], s1);
                }
            }
        }
        p0[t] = s0; p1[t] = s1;
        __syncthreads();
        if (t < 64) {
            g_w0eff[graph * 1600 + tp * 64 + t] =
                p0[t] + p0[64 + t] + p0[128 + t] + p0[192 + t];
            g_w1eff[graph * 1600 + tp * 64 + t] = -0.5f *
                (p1[t] + p1[64 + t] + p1[128 + t] + p1[192 + t]);
        }
    } else {
        float s = 0.f;
        #pragma unroll
        for (int ci = 0; ci < 8; ci++) {
            const int c = cb + ci;
            float a = 0.f;
            #pragma unroll
            for (int tt = 0; tt < 25; tt++)
                a += W0[(c * 25 + tt) * 64 + g] - W1[(c * 25 + tt) * 64 + g];
            s = fmaf(bt[c], a, s);
        }
        p0[t] = s;
        __syncthreads();
        if (t < 64)
            g_c0[graph * 64 + g] =
                p0[g] + p0[64 + g] + p0[128 + g] + p0[192 + g] + bb[g];
    }
}

// ============================================================================
// K1: R rows.  140 blocks = (2 graphs) x (V nodes) x (5 tp-groups); 256 thr.
// ============================================================================
__global__ __launch_bounds__(256) void r_kernel(
    const float* __restrict__ Wp_ecc, const float* __restrict__ bp_ecc,
    const float* __restrict__ Wp_err, const float* __restrict__ bp_err)
{
    const int blk   = blockIdx.x;
    const int graph = (blk >= 80);
    const int rel   = graph ? blk - 80 : blk;
    const int u     = rel / 5;
    const int tpg   = rel % 5;
    const int V     = graph ? 12 : 16;
    const int K     = graph ? 300 : 400;
    const int KP    = graph ? 320 : 448;
    const float* Wp = graph ? Wp_err : Wp_ecc;
    const float* bp = graph ? bp_err : bp_ecc;
    __half* B = graph ? g_B_err : g_B_ecc;

    __shared__ float w0s[5 * 64];
    __shared__ float w1s[5 * 64];
    __shared__ float c0s[64];

    const int t = threadIdx.x;
    for (int i = t; i < 320; i += 256) {
        const int src = graph * 1600 + tpg * 320 + i;
        w0s[i] = g_w0eff[src];
        w1s[i] = g_w1eff[src];
    }
    if (t < 64) c0s[t] = g_c0[graph * 64 + t];
    __syncthreads();

    const int h  = t;
    const int up = (u + 1) % V;
    const int um = (u + V - 1) % V;

    float acc[5] = {0.f, 0.f, 0.f, 0.f, 0.f};
    float pbias = (u == 0 && tpg == 0) ? bp[h] : 0.f;

    const float* WpU = Wp + (size_t)(u  * 64) * 256 + h;
    const float* WpP = Wp + (size_t)(up * 64) * 256 + h;
    const float* WpM = Wp + (size_t)(um * 64) * 256 + h;

    #pragma unroll 4
    for (int gg = 0; gg < 64; gg++) {
        const float wp_u = WpU[gg * 256];
        const float wp_s = WpP[gg * 256] + WpM[gg * 256];
        if (tpg == 0) pbias = fmaf(c0s[gg], wp_u, pbias);
        #pragma unroll
        for (int j = 0; j < 5; j++) {
            acc[j] = fmaf(w0s[j * 64 + gg], wp_u, acc[j]);
            acc[j] = fmaf(w1s[j * 64 + gg], wp_s, acc[j]);
        }
    }

    #pragma unroll
    for (int j = 0; j < 5; j++) {
        const int k = u * 25 + tpg * 5 + j;
        B[(size_t)h * KP + k] = __float2half(acc[j]);
    }
    if (u == 0 && tpg == 0) {
        for (int k = K; k < KP; k++)
            B[(size_t)h * KP + k] = __ushort_as_half((unsigned short)0);
    }
    if (tpg == 0)
        g_bias_part[((graph ? 16 : 0) + u) * 256 + h] = pbias;
}

// ============================================================================
// K2: FUSED GEMM + epilogue. 128 blocks x 64 batch rows; 256 thr (8 warps).
// Per block: ecc GEMM (64x256, K=448) -> smem stash, err GEMM (K=320) ->
// smem stash, then warp-per-row epilogue entirely in-block.
// Kills the 32MB C round-trip + separate epilogue launch + We reloads.
// Warp tiles 32x64 (warp_m = wid&1, warp_n = wid>>2..). Stages: A 8KB + B
// 32KB, double buffered. smem total 219136 B -> 1 block/SM (GEMM is
// HMMA-throughput-bound, not occupancy-bound: ~4 cyc/SM per MMA measured).
// ============================================================================
#define AH_OFF       0
#define BH_OFF       8192
#define STAGE_SZ     40960
#define STASH_E_OFF  81920
#define STASH_STRIDE 264
#define STASH_BYTES  (64 * STASH_STRIDE * 4)          // 67584
#define STASH_R_OFF  (STASH_E_OFF + STASH_BYTES)      // 149504
#define BIAS_E_OFF   (STASH_R_OFF + STASH_BYTES)      // 217088
#define BIAS_R_OFF   (BIAS_E_OFF + 1024)              // 218112
#define FUSED_SMEM   (BIAS_R_OFF + 1024)              // 219136
#define WE_OFF       0            // alias into stage region after GEMMs
#define EHR_OFF      16384

__global__ __launch_bounds__(256, 1) void fused_kernel(
    const float* __restrict__ ecc, const float* __restrict__ err,
    const float* __restrict__ ehr,
    const float* __restrict__ Wa, const float* __restrict__ ba,
    const float* __restrict__ We, const float* __restrict__ be,
    const float* __restrict__ Wf2, const float* __restrict__ bf2,
    float* __restrict__ out)
{
    extern __shared__ char dsm[];
    const uint32_t sb = smem_to_u32(dsm);
    const int tid = threadIdx.x, lane = tid & 31, wid = tid >> 5;
    const int bm = blockIdx.x;              // batch tile: rows bm*64..+63

    // ---- bias sums for both graphs ----
    {
        float s = 0.f;
        #pragma unroll
        for (int u = 0; u < 16; u++) s += g_bias_part[u * 256 + tid];
        ((float*)(dsm + BIAS_E_OFF))[tid] = s;
        s = 0.f;
        #pragma unroll
        for (int u = 0; u < 12; u++) s += g_bias_part[(16 + u) * 256 + tid];
        ((float*)(dsm + BIAS_R_OFF))[tid] = s;
    }

    const int warp_m = wid & 1, warp_n = wid >> 1;
    const int sub = lane >> 3, i8 = lane & 7;
    const int arow_ld = tid >> 2, aq = tid & 3;

    for (int graph = 0; graph < 2; graph++) {
        const int K  = graph ? 300 : 400;
        const int KP = graph ? 320 : 448;
        const int NC = graph ? 5 : 7;
        const float* A = graph ? err : ecc;
        const __half* Bp = graph ? g_B_err : g_B_ecc;
        float* stash = (float*)(dsm + (graph ? STASH_R_OFF : STASH_E_OFF));
        const float* bias_s =
            (const float*)(dsm + (graph ? BIAS_R_OFF : BIAS_E_OFF));

        float acc[2][8][4];
        #pragma unroll
        for (int mi = 0; mi < 2; mi++)
            #pragma unroll
            for (int ni = 0; ni < 8; ni++)
                #pragma unroll
                for (int q = 0; q < 4; q++) acc[mi][ni][q] = 0.f;

        const float* Arow = A + (size_t)(bm * 64 + arow_ld) * K;
        float4 va[4];

        auto ldgA = [&](int c) {
            #pragma unroll
            for (int j = 0; j < 4; j++) {
                const int k = c * 64 + aq * 16 + j * 4;
                va[j] = (k < K) ? *(const float4*)(Arow + k)
                                : make_float4(0.f, 0.f, 0.f, 0.f);
            }
        };
        auto stsA = [&](int c) {
            const uint32_t base = sb + (c & 1) * STAGE_SZ;
            #pragma unroll
            for (int half = 0; half < 2; half++) {
                const float4 p = va[2 * half], q4 = va[2 * half + 1];
                const uint32_t h0 = pack_hi16(p.x, p.y), h1 = pack_hi16(p.z, p.w);
                const uint32_t h2 = pack_hi16(q4.x, q4.y), h3 = pack_hi16(q4.z, q4.w);
                const int g = aq * 2 + half;
                const uint32_t off =
                    (uint32_t)(arow_ld * 8 + (g ^ (arow_ld & 7))) * 16u;
                STS128(h0, h1, h2, h3, base + AH_OFF + off);
            }
        };
        auto issueB = [&](int c) {
            const uint32_t base = sb + (c & 1) * STAGE_SZ;
            #pragma unroll
            for (int it = 0; it < 8; it++) {
                const int idx = tid + it * 256;
                const int row = idx >> 3, g = idx & 7;
                const size_t so = (size_t)row * KP + c * 64 + g * 8;
                const uint32_t off = (uint32_t)(row * 8 + (g ^ (row & 7))) * 16u;
                CP_ASYNC16(base + BH_OFF + off, (const void*)(Bp + so));
            }
            CP_COMMIT();
        };
        auto compute = [&](int c) {
            const uint32_t base = sb + (c & 1) * STAGE_SZ;
            #pragma unroll
            for (int ks = 0; ks < 4; ks++) {
                uint32_t ah[2][4];
                #pragma unroll
                for (int mi = 0; mi < 2; mi++) {
                    const int ar = warp_m * 32 + mi * 16 + i8 + (sub & 1) * 8;
                    const int akg = ks * 2 + (sub >> 1);
                    const uint32_t off =
                        (uint32_t)(ar * 64 + ((akg ^ (ar & 7)) * 8)) * 2u;
                    LDSM_X4(ah[mi][0], ah[mi][1], ah[mi][2], ah[mi][3],
                            base + AH_OFF + off);
                }
                #pragma unroll
                for (int p = 0; p < 4; p++) {
                    const int nn = warp_n * 64 + p * 16 + i8 + (sub >> 1) * 8;
                    const int bkg = ks * 2 + (sub & 1);
                    const uint32_t off =
                        (uint32_t)(nn * 64 + ((bkg ^ (nn & 7)) * 8)) * 2u;
                    uint32_t b0, b1, b2, b3;
                    LDSM_X4(b0, b1, b2, b3, base + BH_OFF + off);
                    #pragma unroll
                    for (int mi = 0; mi < 2; mi++) {
                        MMA16816(acc[mi][2 * p],     ah[mi], b0, b1);
                        MMA16816(acc[mi][2 * p + 1], ah[mi], b2, b3);
                    }
                }
            }
        };

        // pipeline
        issueB(0);
        ldgA(0);
        stsA(0);
        CP_WAIT0();
        __syncthreads();
        ldgA(1); issueB(1);

        for (int c = 0; c < NC; c++) {
            compute(c);
            __syncthreads();
            if (c + 1 < NC) {
                CP_WAIT0();
                stsA(c + 1);
                if (c + 2 < NC) { ldgA(c + 2); issueB(c + 2); }
                __syncthreads();
            }
        }

        // writeback to smem stash (+bias)
        const int g8 = lane >> 2, tg = lane & 3;
        #pragma unroll
        for (int mi = 0; mi < 2; mi++) {
            const int row0 = warp_m * 32 + mi * 16 + g8;
            #pragma unroll
            for (int ni = 0; ni < 8; ni++) {
                const int col = warp_n * 64 + ni * 8 + tg * 2;
                const float b0 = bias_s[col], b1 = bias_s[col + 1];
                *(float2*)(stash + (size_t)row0 * STASH_STRIDE + col) =
                    make_float2(acc[0 + 0][ni][0], 0.f).x == 0.f
                        ? make_float2(acc[mi][ni][0] + b0, acc[mi][ni][1] + b1)
                        : make_float2(acc[mi][ni][0] + b0, acc[mi][ni][1] + b1);
                *(float2*)(stash + (size_t)(row0 + 8) * STASH_STRIDE + col) =
                    make_float2(acc[mi][ni][2] + b0, acc[mi][ni][3] + b1);
            }
        }
        __syncthreads();   // stage + stash settled before next graph / epilogue
    }

    // ---- epilogue (in-block, from smem stashes) ----
    float* We_s  = (float*)(dsm + WE_OFF);
    float* ehr_s = (float*)(dsm + EHR_OFF);
    #pragma unroll
    for (int i = 0; i < 4; i++)
        ((float4*)We_s)[tid + i * 256] = ((const float4*)We)[tid + i * 256];
    #pragma unroll
    for (int i = 0; i < 4; i++)
        ((float4*)ehr_s)[tid + i * 256] =
            ((const float4*)(ehr + (size_t)bm * 64 * 64))[tid + i * 256];
    __syncthreads();

    const float* stash_e = (const float*)(dsm + STASH_E_OFF);
    const float* stash_r = (const float*)(dsm + STASH_R_OFF);
    const float ba0 = ba[0], bf0 = bf2[0];
    float wa[8], wf[8];
    #pragma unroll
    for (int j = 0; j < 8; j++) {
        wa[j] = Wa[lane + 32 * j];
        wf[j] = Wf2[lane + 32 * j];
    }
    const float wfe0 = Wf2[256 + lane], wfe1 = Wf2[256 + lane + 32];
    const float be0 = be[lane], be1 = be[lane + 32];

    for (int q = 0; q < 8; q++) {
        const int row = wid * 8 + q;
        float e[8], r[8];
        #pragma unroll
        for (int j = 0; j < 8; j++) {
            e[j] = stash_e[row * STASH_STRIDE + lane + 32 * j];
            r[j] = stash_r[row * STASH_STRIDE + lane + 32 * j];
        }
        float o0 = be0, o1 = be1;
        #pragma unroll 8
        for (int k = 0; k < 64; k++) {
            const float x = ehr_s[row * 64 + k];
            o0 = fmaf(x, We_s[k * 64 + lane], o0);
            o1 = fmaf(x, We_s[k * 64 + lane + 32], o1);
        }
        o0 = fmaxf(o0, 0.f);
        o1 = fmaxf(o1, 0.f);

        float s = 0.f;
        #pragma unroll
        for (int j = 0; j < 8; j++)
            s = fmaf(tanh_fast(e[j] + r[j]), wa[j], s);
        #pragma unroll
        for (int off = 16; off > 0; off >>= 1)
            s += __shfl_xor_sync(0xffffffffu, s, off);
        const float attn = 1.f / (1.f + __expf(-(s + ba0)));

        float v = o0 * wfe0 + o1 * wfe1;
        #pragma unroll
        for (int j = 0; j < 8; j++) {
            const float f = attn * e[j] + (1.f - attn) * r[j];
            v = fmaf(fmaxf(f, 0.f), wf[j], v);
        }
        #pragma unroll
        for (int off = 16; off > 0; off >>= 1)
            v += __shfl_xor_sync(0xffffffffu, v, off);
        if (lane == 0)
            out[bm * 64 + row] = 1.f / (1.f + __expf(-(v + bf0)));
    }
}

// ============================================================================
extern "C" void kernel_launch(void* const* d_in, const int* in_sizes, int n_in,
                              void* d_out, int out_size) {
    const float* ecc    = (const float*)d_in[0];
    const float* err    = (const float*)d_in[1];
    const float* ehr    = (const float*)d_in[2];
    const float* wt_ecc = (const float*)d_in[3];
    const float* bt_ecc = (const float*)d_in[4];
    const float* wt_err = (const float*)d_in[5];
    const float* bt_err = (const float*)d_in[6];
    const float* W0_ecc = (const float*)d_in[7];
    const float* W1_ecc = (const float*)d_in[8];
    const float* b_ecc  = (const float*)d_in[9];
    const float* W0_err = (const float*)d_in[10];
    const float* W1_err = (const float*)d_in[11];
    const float* b_err  = (const float*)d_in[12];
    const float* Wp_ecc = (const float*)d_in[13];
    const float* bp_ecc = (const float*)d_in[14];
    const float* Wp_err = (const float*)d_in[15];
    const float* bp_err = (const float*)d_in[16];
    const float* Wa     = (const float*)d_in[17];
    const float* ba     = (const float*)d_in[18];
    const float* We     = (const float*)d_in[19];
    const float* be     = (const float*)d_in[20];
    const float* Wf2    = (const float*)d_in[21];
    const float* bf2    = (const float*)d_in[22];

    cudaFuncSetAttribute(fused_kernel,
                         cudaFuncAttributeMaxDynamicSharedMemorySize, FUSED_SMEM);

    dim3 gw(2, 26);
    weff_kernel<<<gw, 256>>>(wt_ecc, bt_ecc, wt_err, bt_err,
                             W0_ecc, W1_ecc, b_ecc, W0_err, W1_err, b_err);
    r_kernel<<<140, 256>>>(Wp_ecc, bp_ecc, Wp_err, bp_err);
    fused_kernel<<<128, 256, FUSED_SMEM>>>(ecc, err, ehr, Wa, ba, We, be,
                                           Wf2, bf2, (float*)d_out);
}

// round 11
// speedup vs baseline: 3.2094x; 1.0936x over previous
#include <cuda_runtime.h>
#include <cuda_fp16.h>
#include <math.h>
#include <stdint.h>

#define B_TOT 8192

// ============================================================================
// Device globals
// ============================================================================
__device__ __align__(16) __half g_B_ecc[256 * 448];   // R^T fp16
__device__ __align__(16) __half g_B_err[256 * 320];
__device__ __align__(16) __half g_WeT[64 * 64];       // We^T fp16 [n][k]
__device__ float g_bias_part[28 * 256];

// ---------------------------------------------------------------------------
#define MMA16816(d, a, b0_, b1_) \
    asm volatile( \
        "mma.sync.aligned.m16n8k16.row.col.f32.f16.f16.f32 " \
        "{%0,%1,%2,%3}, {%4,%5,%6,%7}, {%8,%9}, {%0,%1,%2,%3};" \
        : "+f"((d)[0]), "+f"((d)[1]), "+f"((d)[2]), "+f"((d)[3]) \
        : "r"((a)[0]), "r"((a)[1]), "r"((a)[2]), "r"((a)[3]), \
          "r"(b0_), "r"(b1_))

#define LDSM_X4(r0, r1, r2, r3, addr) \
    asm volatile( \
        "ldmatrix.sync.aligned.m8n8.x4.shared.b16 {%0,%1,%2,%3}, [%4];" \
        : "=r"(r0), "=r"(r1), "=r"(r2), "=r"(r3) : "r"(addr))

#define STS128(r0, r1, r2, r3, addr) \
    asm volatile("st.shared.v4.b32 [%0], {%1, %2, %3, %4};" \
        :: "r"(addr), "r"(r0), "r"(r1), "r"(r2), "r"(r3) : "memory")

#define CP_ASYNC16(dst, src) \
    asm volatile("cp.async.cg.shared.global [%0], [%1], 16;" \
        :: "r"(dst), "l"(src) : "memory")
#define CP_COMMIT() asm volatile("cp.async.commit_group;" ::: "memory")
#define CP_WAIT0()  asm volatile("cp.async.wait_group 0;" ::: "memory")

__device__ __forceinline__ uint32_t smem_to_u32(const void* p) {
    uint32_t a;
    asm("{ .reg .u64 t; cvta.to.shared.u64 t, %1; cvt.u32.u64 %0, t; }"
        : "=r"(a) : "l"(p));
    return a;
}
__device__ __forceinline__ uint32_t pack_hi16(float a, float b) {
    return (uint32_t)__half_as_ushort(__float2half(a)) |
           ((uint32_t)__half_as_ushort(__float2half(b)) << 16);
}
__device__ __forceinline__ float tanh_fast(float x) {
    float y;
    asm("tanh.approx.f32 %0, %1;" : "=f"(y) : "f"(x));
    return y;
}

// ============================================================================
// K1: merged precompute.  grid = 169 blocks, 256 threads.
//  blocks 0..139  : R rows (weff computed INLINE: each thread computes a full
//                   (tp,g) Weff value via ~192 independent L2-hot LDGs; no
//                   reductions, one sync -> latency hidden by 140 blocks)
//  blocks 140..167: c0 + bias_part for (graph, u)
//  block  168     : We^T -> fp16
// ============================================================================
__global__ __launch_bounds__(256) void precompute(
    const float* __restrict__ wt_ecc, const float* __restrict__ bt_ecc,
    const float* __restrict__ wt_err, const float* __restrict__ bt_err,
    const float* __restrict__ W0_ecc, const float* __restrict__ W1_ecc,
    const float* __restrict__ b_ecc,
    const float* __restrict__ W0_err, const float* __restrict__ W1_err,
    const float* __restrict__ b_err,
    const float* __restrict__ Wp_ecc, const float* __restrict__ bp_ecc,
    const float* __restrict__ Wp_err, const float* __restrict__ bp_err,
    const float* __restrict__ We)
{
    const int blk = blockIdx.x;
    const int t   = threadIdx.x;

    if (blk < 140) {
        // ------------------- R rows with inline Weff -------------------
        const int graph = (blk >= 80);
        const int rel   = graph ? blk - 80 : blk;
        const int u     = rel / 5;
        const int tpg   = rel % 5;
        const int V     = graph ? 12 : 16;
        const int K     = graph ? 300 : 400;
        const int KP    = graph ? 320 : 448;
        const float* wt = graph ? wt_err : wt_ecc;
        const float* W0 = graph ? W0_err : W0_ecc;
        const float* W1 = graph ? W1_err : W1_ecc;
        const float* Wp = graph ? Wp_err : Wp_ecc;
        __half* B = graph ? g_B_err : g_B_ecc;

        __shared__ float wts[96];
        __shared__ float w0s[5 * 64];   // [j][g]
        __shared__ float w1s[5 * 64];   // holds -0.5 * Weff1
        if (t < 96) wts[t] = wt[t];
        __syncthreads();

        for (int idx = t; idx < 320; idx += 256) {
            const int j = idx >> 6, g = idx & 63;
            const int tp = tpg * 5 + j;
            float s0 = 0.f, s1 = 0.f;
            #pragma unroll 4
            for (int c = 0; c < 32; c++) {
                #pragma unroll
                for (int k = 0; k < 3; k++) {
                    const int tt = tp - k + 1;
                    if (tt >= 0 && tt < 25) {
                        const float w = wts[c * 3 + k];
                        s0 = fmaf(w, W0[(c * 25 + tt) * 64 + g], s0);
                        s1 = fmaf(w, W1[(c * 25 + tt) * 64 + g], s1);
                    }
                }
            }
            w0s[idx] = s0;
            w1s[idx] = -0.5f * s1;
        }
        __syncthreads();

        const int h  = t;
        const int up = (u + 1) % V;
        const int um = (u + V - 1) % V;

        float acc[5] = {0.f, 0.f, 0.f, 0.f, 0.f};
        const float* WpU = Wp + (size_t)(u  * 64) * 256 + h;
        const float* WpP = Wp + (size_t)(up * 64) * 256 + h;
        const float* WpM = Wp + (size_t)(um * 64) * 256 + h;

        #pragma unroll 4
        for (int gg = 0; gg < 64; gg++) {
            const float wp_u = WpU[gg * 256];
            const float wp_s = WpP[gg * 256] + WpM[gg * 256];
            #pragma unroll
            for (int j = 0; j < 5; j++) {
                acc[j] = fmaf(w0s[j * 64 + gg], wp_u, acc[j]);
                acc[j] = fmaf(w1s[j * 64 + gg], wp_s, acc[j]);
            }
        }

        #pragma unroll
        for (int j = 0; j < 5; j++) {
            const int k = u * 25 + tpg * 5 + j;
            B[(size_t)h * KP + k] = __float2half(acc[j]);
        }
        if (u == 0 && tpg == 0) {
            for (int k = K; k < KP; k++)
                B[(size_t)h * KP + k] = __ushort_as_half((unsigned short)0);
        }
    } else if (blk < 168) {
        // ------------------- c0 + bias_part for (graph, u) -------------------
        const int rel   = blk - 140;
        const int graph = (rel >= 16);
        const int u     = graph ? rel - 16 : rel;
        const float* bt = graph ? bt_err : bt_ecc;
        const float* W0 = graph ? W0_err : W0_ecc;
        const float* W1 = graph ? W1_err : W1_ecc;
        const float* bb = graph ? b_err  : b_ecc;
        const float* Wp = graph ? Wp_err : Wp_ecc;
        const float* bp = graph ? bp_err : bp_ecc;

        __shared__ float part[256];
        __shared__ float c0s[64];

        const int g = t & 63, cb = (t >> 6) * 8;
        float s = 0.f;
        #pragma unroll
        for (int ci = 0; ci < 8; ci++) {
            const int c = cb + ci;
            float a = 0.f;
            #pragma unroll
            for (int tt = 0; tt < 25; tt++)
                a += W0[(c * 25 + tt) * 64 + g] - W1[(c * 25 + tt) * 64 + g];
            s = fmaf(bt[c], a, s);
        }
        part[t] = s;
        __syncthreads();
        if (t < 64)
            c0s[g] = part[g] + part[64 + g] + part[128 + g] + part[192 + g] + bb[g];
        __syncthreads();

        const int h = t;
        float pbias = (u == 0) ? bp[h] : 0.f;
        const float* WpU = Wp + (size_t)(u * 64) * 256 + h;
        #pragma unroll 8
        for (int gg = 0; gg < 64; gg++)
            pbias = fmaf(c0s[gg], WpU[gg * 256], pbias);
        g_bias_part[((graph ? 16 : 0) + u) * 256 + h] = pbias;
    } else {
        // ------------------- We^T fp16 -------------------
        for (int i = t; i < 4096; i += 256) {
            const int n = i >> 6, k = i & 63;
            g_WeT[n * 64 + k] = __float2half(We[k * 64 + n]);
        }
    }
}

// ============================================================================
// K2: FUSED GEMM + ehr-MMA + epilogue. 128 blocks x 64 batch rows; 256 thr.
// ============================================================================
#define AH_OFF       0
#define BH_OFF       8192
#define STAGE_SZ     40960
#define EHRP_OFF     STAGE_SZ                         // alias stage1 (16KB)
#define STASH_E_OFF  81920
#define STASH_STRIDE 264
#define STASH_BYTES  (64 * STASH_STRIDE * 4)          // 67584
#define STASH_R_OFF  (STASH_E_OFF + STASH_BYTES)      // 149504
#define BIAS_E_OFF   (STASH_R_OFF + STASH_BYTES)      // 217088
#define BIAS_R_OFF   (BIAS_E_OFF + 1024)              // 218112
#define FUSED_SMEM   (BIAS_R_OFF + 1024)              // 219136

__global__ __launch_bounds__(256, 1) void fused_kernel(
    const float* __restrict__ ecc, const float* __restrict__ err,
    const float* __restrict__ ehr,
    const float* __restrict__ Wa, const float* __restrict__ ba,
    const float* __restrict__ be,
    const float* __restrict__ Wf2, const float* __restrict__ bf2,
    float* __restrict__ out)
{
    extern __shared__ char dsm[];
    const uint32_t sb = smem_to_u32(dsm);
    const int tid = threadIdx.x, lane = tid & 31, wid = tid >> 5;
    const int bm = blockIdx.x;              // batch tile: rows bm*64..+63

    // ---- bias sums for both graphs ----
    {
        float s = 0.f;
        #pragma unroll
        for (int u = 0; u < 16; u++) s += g_bias_part[u * 256 + tid];
        ((float*)(dsm + BIAS_E_OFF))[tid] = s;
        s = 0.f;
        #pragma unroll
        for (int u = 0; u < 12; u++) s += g_bias_part[(16 + u) * 256 + tid];
        ((float*)(dsm + BIAS_R_OFF))[tid] = s;
    }

    const int warp_m = wid & 1, warp_n = wid >> 1;
    const int sub = lane >> 3, i8 = lane & 7;
    const int arow_ld = tid >> 2, aq = tid & 3;

    for (int graph = 0; graph < 2; graph++) {
        const int K  = graph ? 300 : 400;
        const int KP = graph ? 320 : 448;
        const int NC = graph ? 5 : 7;
        const float* A = graph ? err : ecc;
        const __half* Bp = graph ? g_B_err : g_B_ecc;
        float* stash = (float*)(dsm + (graph ? STASH_R_OFF : STASH_E_OFF));
        const float* bias_s =
            (const float*)(dsm + (graph ? BIAS_R_OFF : BIAS_E_OFF));

        float acc[2][8][4];
        #pragma unroll
        for (int mi = 0; mi < 2; mi++)
            #pragma unroll
            for (int ni = 0; ni < 8; ni++)
                #pragma unroll
                for (int q = 0; q < 4; q++) acc[mi][ni][q] = 0.f;

        const float* Arow = A + (size_t)(bm * 64 + arow_ld) * K;
        float4 va[4];

        auto ldgA = [&](int c) {
            #pragma unroll
            for (int j = 0; j < 4; j++) {
                const int k = c * 64 + aq * 16 + j * 4;
                va[j] = (k < K) ? *(const float4*)(Arow + k)
                                : make_float4(0.f, 0.f, 0.f, 0.f);
            }
        };
        auto stsA = [&](int c) {
            const uint32_t base = sb + (c & 1) * STAGE_SZ;
            #pragma unroll
            for (int half = 0; half < 2; half++) {
                const float4 p = va[2 * half], q4 = va[2 * half + 1];
                const uint32_t h0 = pack_hi16(p.x, p.y), h1 = pack_hi16(p.z, p.w);
                const uint32_t h2 = pack_hi16(q4.x, q4.y), h3 = pack_hi16(q4.z, q4.w);
                const int g = aq * 2 + half;
                const uint32_t off =
                    (uint32_t)(arow_ld * 8 + (g ^ (arow_ld & 7))) * 16u;
                STS128(h0, h1, h2, h3, base + AH_OFF + off);
            }
        };
        auto issueB = [&](int c) {
            const uint32_t base = sb + (c & 1) * STAGE_SZ;
            #pragma unroll
            for (int it = 0; it < 8; it++) {
                const int idx = tid + it * 256;
                const int row = idx >> 3, g = idx & 7;
                const size_t so = (size_t)row * KP + c * 64 + g * 8;
                const uint32_t off = (uint32_t)(row * 8 + (g ^ (row & 7))) * 16u;
                CP_ASYNC16(base + BH_OFF + off, (const void*)(Bp + so));
            }
            CP_COMMIT();
        };
        auto compute = [&](int c) {
            const uint32_t base = sb + (c & 1) * STAGE_SZ;
            #pragma unroll
            for (int ks = 0; ks < 4; ks++) {
                uint32_t ah[2][4];
                #pragma unroll
                for (int mi = 0; mi < 2; mi++) {
                    const int ar = warp_m * 32 + mi * 16 + i8 + (sub & 1) * 8;
                    const int akg = ks * 2 + (sub >> 1);
                    const uint32_t off =
                        (uint32_t)(ar * 64 + ((akg ^ (ar & 7)) * 8)) * 2u;
                    LDSM_X4(ah[mi][0], ah[mi][1], ah[mi][2], ah[mi][3],
                            base + AH_OFF + off);
                }
                #pragma unroll
                for (int p = 0; p < 4; p++) {
                    const int nn = warp_n * 64 + p * 16 + i8 + (sub >> 1) * 8;
                    const int bkg = ks * 2 + (sub & 1);
                    const uint32_t off =
                        (uint32_t)(nn * 64 + ((bkg ^ (nn & 7)) * 8)) * 2u;
                    uint32_t b0, b1, b2, b3;
                    LDSM_X4(b0, b1, b2, b3, base + BH_OFF + off);
                    #pragma unroll
                    for (int mi = 0; mi < 2; mi++) {
                        MMA16816(acc[mi][2 * p],     ah[mi], b0, b1);
                        MMA16816(acc[mi][2 * p + 1], ah[mi], b2, b3);
                    }
                }
            }
        };

        // pipeline
        issueB(0);
        ldgA(0);
        stsA(0);
        CP_WAIT0();
        __syncthreads();
        ldgA(1); issueB(1);

        for (int c = 0; c < NC; c++) {
            compute(c);
            __syncthreads();
            if (c + 1 < NC) {
                CP_WAIT0();
                stsA(c + 1);
                if (c + 2 < NC) { ldgA(c + 2); issueB(c + 2); }
                __syncthreads();
            }
        }

        // writeback to smem stash (+bias)
        const int g8 = lane >> 2, tg = lane & 3;
        #pragma unroll
        for (int mi = 0; mi < 2; mi++) {
            const int row0 = warp_m * 32 + mi * 16 + g8;
            #pragma unroll
            for (int ni = 0; ni < 8; ni++) {
                const int col = warp_n * 64 + ni * 8 + tg * 2;
                const float b0 = bias_s[col], b1 = bias_s[col + 1];
                *(float2*)(stash + (size_t)row0 * STASH_STRIDE + col) =
                    make_float2(acc[mi][ni][0] + b0, acc[mi][ni][1] + b1);
                *(float2*)(stash + (size_t)(row0 + 8) * STASH_STRIDE + col) =
                    make_float2(acc[mi][ni][2] + b0, acc[mi][ni][3] + b1);
            }
        }
        __syncthreads();
    }

    // ---- ehr mini-GEMM: ehrp = relu(ehr @ We + be) via HMMA ----
    // A: 64x64 ehr tile (stage0 A region), B: We^T (stage0 B region).
    {
        // issue We^T (64 rows x 8 granules = 512 cp.asyncs)
        #pragma unroll
        for (int it = 0; it < 2; it++) {
            const int idx = tid + it * 256;
            const int row = idx >> 3, g = idx & 7;
            const size_t so = (size_t)row * 64 + g * 8;
            const uint32_t off = (uint32_t)(row * 8 + (g ^ (row & 7))) * 16u;
            CP_ASYNC16(sb + BH_OFF + off, (const void*)(g_WeT + so));
        }
        CP_COMMIT();
        // A: ehr rows (K=64 exactly one chunk)
        const float* Erow = ehr + (size_t)(bm * 64 + arow_ld) * 64;
        float4 va[4];
        #pragma unroll
        for (int j = 0; j < 4; j++)
            va[j] = *(const float4*)(Erow + aq * 16 + j * 4);
        #pragma unroll
        for (int half = 0; half < 2; half++) {
            const float4 p = va[2 * half], q4 = va[2 * half + 1];
            const uint32_t h0 = pack_hi16(p.x, p.y), h1 = pack_hi16(p.z, p.w);
            const uint32_t h2 = pack_hi16(q4.x, q4.y), h3 = pack_hi16(q4.z, q4.w);
            const int g = aq * 2 + half;
            const uint32_t off =
                (uint32_t)(arow_ld * 8 + (g ^ (arow_ld & 7))) * 16u;
            STS128(h0, h1, h2, h3, sb + AH_OFF + off);
        }
        CP_WAIT0();
        __syncthreads();

        float accH[2][2][4];
        #pragma unroll
        for (int mi = 0; mi < 2; mi++)
            #pragma unroll
            for (int ni = 0; ni < 2; ni++)
                #pragma unroll
                for (int q = 0; q < 4; q++) accH[mi][ni][q] = 0.f;

        #pragma unroll
        for (int ks = 0; ks < 4; ks++) {
            uint32_t ah[2][4];
            #pragma unroll
            for (int mi = 0; mi < 2; mi++) {
                const int ar = warp_m * 32 + mi * 16 + i8 + (sub & 1) * 8;
                const int akg = ks * 2 + (sub >> 1);
                const uint32_t off =
                    (uint32_t)(ar * 64 + ((akg ^ (ar & 7)) * 8)) * 2u;
                LDSM_X4(ah[mi][0], ah[mi][1], ah[mi][2], ah[mi][3],
                        sb + AH_OFF + off);
            }
            const int nn = warp_n * 16 + i8 + (sub >> 1) * 8;   // < 64
            const int bkg = ks * 2 + (sub & 1);
            const uint32_t off =
                (uint32_t)(nn * 64 + ((bkg ^ (nn & 7)) * 8)) * 2u;
            uint32_t b0, b1, b2, b3;
            LDSM_X4(b0, b1, b2, b3, sb + BH_OFF + off);
            #pragma unroll
            for (int mi = 0; mi < 2; mi++) {
                MMA16816(accH[mi][0], ah[mi], b0, b1);
                MMA16816(accH[mi][1], ah[mi], b2, b3);
            }
        }

        // writeback: relu(acc + be[col]) -> ehrp stash [row][64]
        float* ehrp = (float*)(dsm + EHRP_OFF);
        const int g8 = lane >> 2, tg = lane & 3;
        #pragma unroll
        for (int mi = 0; mi < 2; mi++) {
            const int row0 = warp_m * 32 + mi * 16 + g8;
            #pragma unroll
            for (int ni = 0; ni < 2; ni++) {
                const int col = warp_n * 16 + ni * 8 + tg * 2;
                const float b0 = __ldg(be + col), b1 = __ldg(be + col + 1);
                ehrp[row0 * 64 + col]       = fmaxf(accH[mi][ni][0] + b0, 0.f);
                ehrp[row0 * 64 + col + 1]   = fmaxf(accH[mi][ni][1] + b1, 0.f);
                ehrp[(row0 + 8) * 64 + col] = fmaxf(accH[mi][ni][2] + b0, 0.f);
                ehrp[(row0 + 8) * 64 + col + 1] =
                    fmaxf(accH[mi][ni][3] + b1, 0.f);
            }
        }
    }
    __syncthreads();

    // ---- epilogue (warp-per-row, all from smem) ----
    const float* stash_e = (const float*)(dsm + STASH_E_OFF);
    const float* stash_r = (const float*)(dsm + STASH_R_OFF);
    const float* ehrp    = (const float*)(dsm + EHRP_OFF);
    const float ba0 = ba[0], bf0 = bf2[0];
    float wa[8], wf[8];
    #pragma unroll
    for (int j = 0; j < 8; j++) {
        wa[j] = Wa[lane + 32 * j];
        wf[j] = Wf2[lane + 32 * j];
    }
    const float wfe0 = Wf2[256 + lane], wfe1 = Wf2[256 + lane + 32];

    #pragma unroll 2
    for (int q = 0; q < 8; q++) {
        const int row = wid * 8 + q;
        float e[8], r[8];
        #pragma unroll
        for (int j = 0; j < 8; j++) {
            e[j] = stash_e[row * STASH_STRIDE + lane + 32 * j];
            r[j] = stash_r[row * STASH_STRIDE + lane + 32 * j];
        }
        const float o0 = ehrp[row * 64 + lane];
        const float o1 = ehrp[row * 64 + lane + 32];

        float s = 0.f;
        #pragma unroll
        for (int j = 0; j < 8; j++)
            s = fmaf(tanh_fast(e[j] + r[j]), wa[j], s);
        #pragma unroll
        for (int off = 16; off > 0; off >>= 1)
            s += __shfl_xor_sync(0xffffffffu, s, off);
        const float attn = 1.f / (1.f + __expf(-(s + ba0)));

        float v = o0 * wfe0 + o1 * wfe1;
        #pragma unroll
        for (int j = 0; j < 8; j++) {
            const float f = attn * e[j] + (1.f - attn) * r[j];
            v = fmaf(fmaxf(f, 0.f), wf[j], v);
        }
        #pragma unroll
        for (int off = 16; off > 0; off >>= 1)
            v += __shfl_xor_sync(0xffffffffu, v, off);
        if (lane == 0)
            out[bm * 64 + row] = 1.f / (1.f + __expf(-(v + bf0)));
    }
}

// ============================================================================
extern "C" void kernel_launch(void* const* d_in, const int* in_sizes, int n_in,
                              void* d_out, int out_size) {
    const float* ecc    = (const float*)d_in[0];
    const float* err    = (const float*)d_in[1];
    const float* ehr    = (const float*)d_in[2];
    const float* wt_ecc = (const float*)d_in[3];
    const float* bt_ecc = (const float*)d_in[4];
    const float* wt_err = (const float*)d_in[5];
    const float* bt_err = (const float*)d_in[6];
    const float* W0_ecc = (const float*)d_in[7];
    const float* W1_ecc = (const float*)d_in[8];
    const float* b_ecc  = (const float*)d_in[9];
    const float* W0_err = (const float*)d_in[10];
    const float* W1_err = (const float*)d_in[11];
    const float* b_err  = (const float*)d_in[12];
    const float* Wp_ecc = (const float*)d_in[13];
    const float* bp_ecc = (const float*)d_in[14];
    const float* Wp_err = (const float*)d_in[15];
    const float* bp_err = (const float*)d_in[16];
    const float* Wa     = (const float*)d_in[17];
    const float* ba     = (const float*)d_in[18];
    const float* We     = (const float*)d_in[19];
    const float* be     = (const float*)d_in[20];
    const float* Wf2    = (const float*)d_in[21];
    const float* bf2    = (const float*)d_in[22];

    cudaFuncSetAttribute(fused_kernel,
                         cudaFuncAttributeMaxDynamicSharedMemorySize, FUSED_SMEM);

    precompute<<<169, 256>>>(wt_ecc, bt_ecc, wt_err, bt_err,
                             W0_ecc, W1_ecc, b_ecc, W0_err, W1_err, b_err,
                             Wp_ecc, bp_ecc, Wp_err, bp_err, We);
    fused_kernel<<<128, 256, FUSED_SMEM>>>(ecc, err, ehr, Wa, ba, be,
                                           Wf2, bf2, (float*)d_out);
}

// round 12
// speedup vs baseline: 3.2803x; 1.0221x over previous
#include <cuda_runtime.h>
#include <cuda_fp16.h>
#include <math.h>
#include <stdint.h>

#define B_TOT 8192

// ============================================================================
// Device globals
// ============================================================================
__device__ __align__(16) __half g_B_ecc[256 * 448];   // R^T fp16
__device__ __align__(16) __half g_B_err[256 * 320];
__device__ __align__(16) __half g_WeT[64 * 64];       // We^T fp16 [n][k]
__device__ __align__(16) __half g_Ah_ecc[B_TOT * 448]; // ecc fp16, padded
__device__ __align__(16) __half g_Ah_err[B_TOT * 320];
__device__ __align__(16) __half g_Ah_ehr[B_TOT * 64];
__device__ float g_bias_part[28 * 256];

// ---------------------------------------------------------------------------
#define MMA16816(d, a, b0_, b1_) \
    asm volatile( \
        "mma.sync.aligned.m16n8k16.row.col.f32.f16.f16.f32 " \
        "{%0,%1,%2,%3}, {%4,%5,%6,%7}, {%8,%9}, {%0,%1,%2,%3};" \
        : "+f"((d)[0]), "+f"((d)[1]), "+f"((d)[2]), "+f"((d)[3]) \
        : "r"((a)[0]), "r"((a)[1]), "r"((a)[2]), "r"((a)[3]), \
          "r"(b0_), "r"(b1_))

#define LDSM_X4(r0, r1, r2, r3, addr) \
    asm volatile( \
        "ldmatrix.sync.aligned.m8n8.x4.shared.b16 {%0,%1,%2,%3}, [%4];" \
        : "=r"(r0), "=r"(r1), "=r"(r2), "=r"(r3) : "r"(addr))

#define CP_ASYNC16(dst, src) \
    asm volatile("cp.async.cg.shared.global [%0], [%1], 16;" \
        :: "r"(dst), "l"(src) : "memory")
#define CP_COMMIT() asm volatile("cp.async.commit_group;" ::: "memory")
#define CP_WAIT0()  asm volatile("cp.async.wait_group 0;" ::: "memory")
#define CP_WAIT1()  asm volatile("cp.async.wait_group 1;" ::: "memory")

__device__ __forceinline__ uint32_t smem_to_u32(const void* p) {
    uint32_t a;
    asm("{ .reg .u64 t; cvta.to.shared.u64 t, %1; cvt.u32.u64 %0, t; }"
        : "=r"(a) : "l"(p));
    return a;
}
__device__ __forceinline__ uint32_t pack_hi16(float a, float b) {
    return (uint32_t)__half_as_ushort(__float2half(a)) |
           ((uint32_t)__half_as_ushort(__float2half(b)) << 16);
}
__device__ __forceinline__ float tanh_fast(float x) {
    float y;
    asm("tanh.approx.f32 %0, %1;" : "=f"(y) : "f"(x));
    return y;
}

// ============================================================================
// K1: merged precompute + fp16 conversions.  grid = 745 blocks x 256 thr.
//  0..139   : R rows (Weff inline)      140..167: c0 + bias_part
//  168      : We^T fp16                 169..424: ecc -> fp16 (32 rows/blk)
//  425..680 : err -> fp16 (32 rows/blk) 681..744: ehr -> fp16 (128 rows/blk)
// ============================================================================
__global__ __launch_bounds__(256) void precompute(
    const float* __restrict__ ecc, const float* __restrict__ err,
    const float* __restrict__ ehr,
    const float* __restrict__ wt_ecc, const float* __restrict__ bt_ecc,
    const float* __restrict__ wt_err, const float* __restrict__ bt_err,
    const float* __restrict__ W0_ecc, const float* __restrict__ W1_ecc,
    const float* __restrict__ b_ecc,
    const float* __restrict__ W0_err, const float* __restrict__ W1_err,
    const float* __restrict__ b_err,
    const float* __restrict__ Wp_ecc, const float* __restrict__ bp_ecc,
    const float* __restrict__ Wp_err, const float* __restrict__ bp_err,
    const float* __restrict__ We)
{
    const int blk = blockIdx.x;
    const int t   = threadIdx.x;

    if (blk < 140) {
        // ------------------- R rows with inline Weff -------------------
        const int graph = (blk >= 80);
        const int rel   = graph ? blk - 80 : blk;
        const int u     = rel / 5;
        const int tpg   = rel % 5;
        const int V     = graph ? 12 : 16;
        const int K     = graph ? 300 : 400;
        const int KP    = graph ? 320 : 448;
        const float* wt = graph ? wt_err : wt_ecc;
        const float* W0 = graph ? W0_err : W0_ecc;
        const float* W1 = graph ? W1_err : W1_ecc;
        const float* Wp = graph ? Wp_err : Wp_ecc;
        __half* B = graph ? g_B_err : g_B_ecc;

        __shared__ float wts[96];
        __shared__ float w0s[5 * 64];
        __shared__ float w1s[5 * 64];
        if (t < 96) wts[t] = wt[t];
        __syncthreads();

        for (int idx = t; idx < 320; idx += 256) {
            const int j = idx >> 6, g = idx & 63;
            const int tp = tpg * 5 + j;
            float s0 = 0.f, s1 = 0.f;
            #pragma unroll 4
            for (int c = 0; c < 32; c++) {
                #pragma unroll
                for (int k = 0; k < 3; k++) {
                    const int tt = tp - k + 1;
                    if (tt >= 0 && tt < 25) {
                        const float w = wts[c * 3 + k];
                        s0 = fmaf(w, W0[(c * 25 + tt) * 64 + g], s0);
                        s1 = fmaf(w, W1[(c * 25 + tt) * 64 + g], s1);
                    }
                }
            }
            w0s[idx] = s0;
            w1s[idx] = -0.5f * s1;
        }
        __syncthreads();

        const int h  = t;
        const int up = (u + 1) % V;
        const int um = (u + V - 1) % V;

        float acc[5] = {0.f, 0.f, 0.f, 0.f, 0.f};
        const float* WpU = Wp + (size_t)(u  * 64) * 256 + h;
        const float* WpP = Wp + (size_t)(up * 64) * 256 + h;
        const float* WpM = Wp + (size_t)(um * 64) * 256 + h;

        #pragma unroll 4
        for (int gg = 0; gg < 64; gg++) {
            const float wp_u = WpU[gg * 256];
            const float wp_s = WpP[gg * 256] + WpM[gg * 256];
            #pragma unroll
            for (int j = 0; j < 5; j++) {
                acc[j] = fmaf(w0s[j * 64 + gg], wp_u, acc[j]);
                acc[j] = fmaf(w1s[j * 64 + gg], wp_s, acc[j]);
            }
        }

        #pragma unroll
        for (int j = 0; j < 5; j++) {
            const int k = u * 25 + tpg * 5 + j;
            B[(size_t)h * KP + k] = __float2half(acc[j]);
        }
        if (u == 0 && tpg == 0) {
            for (int k = K; k < KP; k++)
                B[(size_t)h * KP + k] = __ushort_as_half((unsigned short)0);
        }
    } else if (blk < 168) {
        // ------------------- c0 + bias_part -------------------
        const int rel   = blk - 140;
        const int graph = (rel >= 16);
        const int u     = graph ? rel - 16 : rel;
        const float* bt = graph ? bt_err : bt_ecc;
        const float* W0 = graph ? W0_err : W0_ecc;
        const float* W1 = graph ? W1_err : W1_ecc;
        const float* bb = graph ? b_err  : b_ecc;
        const float* Wp = graph ? Wp_err : Wp_ecc;
        const float* bp = graph ? bp_err : bp_ecc;

        __shared__ float part[256];
        __shared__ float c0s[64];

        const int g = t & 63, cb = (t >> 6) * 8;
        float s = 0.f;
        #pragma unroll
        for (int ci = 0; ci < 8; ci++) {
            const int c = cb + ci;
            float a = 0.f;
            #pragma unroll
            for (int tt = 0; tt < 25; tt++)
                a += W0[(c * 25 + tt) * 64 + g] - W1[(c * 25 + tt) * 64 + g];
            s = fmaf(bt[c], a, s);
        }
        part[t] = s;
        __syncthreads();
        if (t < 64)
            c0s[g] = part[g] + part[64 + g] + part[128 + g] + part[192 + g] + bb[g];
        __syncthreads();

        const int h = t;
        float pbias = (u == 0) ? bp[h] : 0.f;
        const float* WpU = Wp + (size_t)(u * 64) * 256 + h;
        #pragma unroll 8
        for (int gg = 0; gg < 64; gg++)
            pbias = fmaf(c0s[gg], WpU[gg * 256], pbias);
        g_bias_part[((graph ? 16 : 0) + u) * 256 + h] = pbias;
    } else if (blk == 168) {
        // ------------------- We^T fp16 -------------------
        for (int i = t; i < 4096; i += 256) {
            const int n = i >> 6, k = i & 63;
            g_WeT[n * 64 + k] = __float2half(We[k * 64 + n]);
        }
    } else if (blk < 425) {
        // ------------------- ecc -> fp16, KP=448 -------------------
        const int r0 = (blk - 169) * 32;
        for (int idx = t; idx < 32 * 56; idx += 256) {
            const int row = idx / 56, gg = idx - row * 56;
            uint4 v = make_uint4(0u, 0u, 0u, 0u);
            if (gg < 50) {
                const float* s = ecc + (size_t)(r0 + row) * 400 + gg * 8;
                const float4 a = *(const float4*)s;
                const float4 b = *(const float4*)(s + 4);
                v.x = pack_hi16(a.x, a.y); v.y = pack_hi16(a.z, a.w);
                v.z = pack_hi16(b.x, b.y); v.w = pack_hi16(b.z, b.w);
            }
            *(uint4*)(g_Ah_ecc + (size_t)(r0 + row) * 448 + gg * 8) = v;
        }
    } else if (blk < 681) {
        // ------------------- err -> fp16, KP=320 (300 real) -------------------
        const int r0 = (blk - 425) * 32;
        for (int idx = t; idx < 32 * 40; idx += 256) {
            const int row = idx / 40, gg = idx - row * 40;
            uint4 v = make_uint4(0u, 0u, 0u, 0u);
            if (gg < 37) {
                const float* s = err + (size_t)(r0 + row) * 300 + gg * 8;
                const float4 a = *(const float4*)s;
                const float4 b = *(const float4*)(s + 4);
                v.x = pack_hi16(a.x, a.y); v.y = pack_hi16(a.z, a.w);
                v.z = pack_hi16(b.x, b.y); v.w = pack_hi16(b.z, b.w);
            } else if (gg == 37) {
                const float* s = err + (size_t)(r0 + row) * 300 + 296;
                v.x = pack_hi16(s[0], s[1]); v.y = pack_hi16(s[2], s[3]);
            }
            *(uint4*)(g_Ah_err + (size_t)(r0 + row) * 320 + gg * 8) = v;
        }
    } else {
        // ------------------- ehr -> fp16 -------------------
        const int r0 = (blk - 681) * 128;
        for (int idx = t; idx < 128 * 8; idx += 256) {
            const int row = idx >> 3, gg = idx & 7;
            const float* s = ehr + (size_t)(r0 + row) * 64 + gg * 8;
            const float4 a = *(const float4*)s;
            const float4 b = *(const float4*)(s + 4);
            uint4 v;
            v.x = pack_hi16(a.x, a.y); v.y = pack_hi16(a.z, a.w);
            v.z = pack_hi16(b.x, b.y); v.w = pack_hi16(b.z, b.w);
            *(uint4*)(g_Ah_ehr + (size_t)(r0 + row) * 64 + gg * 8) = v;
        }
    }
}

// ============================================================================
// K2: FUSED GEMM + ehr-MMA + epilogue. 128 blocks x 64 batch rows; 256 thr.
// All-cp.async, 3-stage pipeline, ONE sync per K-chunk. fp16 stashes.
// ============================================================================
#define A_OFF        0
#define B_OFF        8192
#define STAGE_SZ     40960
#define EHRP_OFF     40960                            // fp32 16KB in stage1
#define STASH_E_OFF  122880                           // halves, 64*264*2 B
#define STASH_STRIDE 264
#define STASH_R_OFF  156672
#define BIAS_E_OFF   190464
#define BIAS_R_OFF   191488
#define FUSED_SMEM   192512

__global__ __launch_bounds__(256, 1) void fused_kernel(
    const float* __restrict__ Wa, const float* __restrict__ ba,
    const float* __restrict__ be,
    const float* __restrict__ Wf2, const float* __restrict__ bf2,
    float* __restrict__ out)
{
    extern __shared__ char dsm[];
    const uint32_t sb = smem_to_u32(dsm);
    const int tid = threadIdx.x, lane = tid & 31, wid = tid >> 5;
    const int bm = blockIdx.x;

    // ---- bias sums ----
    {
        float s = 0.f;
        #pragma unroll
        for (int u = 0; u < 16; u++) s += g_bias_part[u * 256 + tid];
        ((float*)(dsm + BIAS_E_OFF))[tid] = s;
        s = 0.f;
        #pragma unroll
        for (int u = 0; u < 12; u++) s += g_bias_part[(16 + u) * 256 + tid];
        ((float*)(dsm + BIAS_R_OFF))[tid] = s;
    }

    const int warp_m = wid & 1, warp_n = wid >> 1;
    const int sub = lane >> 3, i8 = lane & 7;

    for (int graph = 0; graph < 2; graph++) {
        const int KP = graph ? 320 : 448;
        const int NC = graph ? 5 : 7;
        const __half* Ap = graph ? g_Ah_err : g_Ah_ecc;
        const __half* Bp = graph ? g_B_err : g_B_ecc;
        __half* stash = (__half*)(dsm + (graph ? STASH_R_OFF : STASH_E_OFF));
        const float* bias_s =
            (const float*)(dsm + (graph ? BIAS_R_OFF : BIAS_E_OFF));

        float acc[2][8][4];
        #pragma unroll
        for (int mi = 0; mi < 2; mi++)
            #pragma unroll
            for (int ni = 0; ni < 8; ni++)
                #pragma unroll
                for (int q = 0; q < 4; q++) acc[mi][ni][q] = 0.f;

        auto issueAB = [&](int c) {
            const uint32_t base = sb + (c % 3) * STAGE_SZ;
            #pragma unroll
            for (int it = 0; it < 2; it++) {
                const int idx = tid + it * 256;
                const int row = idx >> 3, g = idx & 7;
                const __half* src =
                    Ap + (size_t)(bm * 64 + row) * KP + c * 64 + g * 8;
                const uint32_t off = (uint32_t)(row * 8 + (g ^ (row & 7))) * 16u;
                CP_ASYNC16(base + A_OFF + off, (const void*)src);
            }
            #pragma unroll
            for (int it = 0; it < 8; it++) {
                const int idx = tid + it * 256;
                const int row = idx >> 3, g = idx & 7;
                const __half* src = Bp + (size_t)row * KP + c * 64 + g * 8;
                const uint32_t off = (uint32_t)(row * 8 + (g ^ (row & 7))) * 16u;
                CP_ASYNC16(base + B_OFF + off, (const void*)src);
            }
            CP_COMMIT();
        };
        auto compute = [&](int c) {
            const uint32_t base = sb + (c % 3) * STAGE_SZ;
            #pragma unroll
            for (int ks = 0; ks < 4; ks++) {
                uint32_t ah[2][4];
                #pragma unroll
                for (int mi = 0; mi < 2; mi++) {
                    const int ar = warp_m * 32 + mi * 16 + i8 + (sub & 1) * 8;
                    const int akg = ks * 2 + (sub >> 1);
                    const uint32_t off =
                        (uint32_t)(ar * 64 + ((akg ^ (ar & 7)) * 8)) * 2u;
                    LDSM_X4(ah[mi][0], ah[mi][1], ah[mi][2], ah[mi][3],
                            base + A_OFF + off);
                }
                #pragma unroll
                for (int p = 0; p < 4; p++) {
                    const int nn = warp_n * 64 + p * 16 + i8 + (sub >> 1) * 8;
                    const int bkg = ks * 2 + (sub & 1);
                    const uint32_t off =
                        (uint32_t)(nn * 64 + ((bkg ^ (nn & 7)) * 8)) * 2u;
                    uint32_t b0, b1, b2, b3;
                    LDSM_X4(b0, b1, b2, b3, base + B_OFF + off);
                    #pragma unroll
                    for (int mi = 0; mi < 2; mi++) {
                        MMA16816(acc[mi][2 * p],     ah[mi], b0, b1);
                        MMA16816(acc[mi][2 * p + 1], ah[mi], b2, b3);
                    }
                }
            }
        };

        // ---- 3-stage pipeline, one sync per chunk ----
        issueAB(0);
        issueAB(1);
        for (int c = 0; c < NC; c++) {
            if (c + 1 < NC) { CP_WAIT1(); } else { CP_WAIT0(); }
            __syncthreads();
            if (c + 2 < NC) issueAB(c + 2);
            compute(c);
        }
        __syncthreads();   // all warps done with stages before reuse

        // ---- writeback to fp16 stash (+bias) ----
        const int g8 = lane >> 2, tg = lane & 3;
        #pragma unroll
        for (int mi = 0; mi < 2; mi++) {
            const int row0 = warp_m * 32 + mi * 16 + g8;
            #pragma unroll
            for (int ni = 0; ni < 8; ni++) {
                const int col = warp_n * 64 + ni * 8 + tg * 2;
                const float b0 = bias_s[col], b1 = bias_s[col + 1];
                *(__half2*)(stash + row0 * STASH_STRIDE + col) =
                    __floats2half2_rn(acc[mi][ni][0] + b0, acc[mi][ni][1] + b1);
                *(__half2*)(stash + (row0 + 8) * STASH_STRIDE + col) =
                    __floats2half2_rn(acc[mi][ni][2] + b0, acc[mi][ni][3] + b1);
            }
        }
    }

    // ---- ehr mini-GEMM: ehrp = relu(ehr @ We + be), all cp.async ----
    {
        #pragma unroll
        for (int it = 0; it < 2; it++) {
            const int idx = tid + it * 256;
            const int row = idx >> 3, g = idx & 7;
            const __half* src = g_Ah_ehr + (size_t)(bm * 64 + row) * 64 + g * 8;
            const uint32_t off = (uint32_t)(row * 8 + (g ^ (row & 7))) * 16u;
            CP_ASYNC16(sb + A_OFF + off, (const void*)src);
        }
        #pragma unroll
        for (int it = 0; it < 2; it++) {
            const int idx = tid + it * 256;
            const int row = idx >> 3, g = idx & 7;
            const __half* src = g_WeT + (size_t)row * 64 + g * 8;
            const uint32_t off = (uint32_t)(row * 8 + (g ^ (row & 7))) * 16u;
            CP_ASYNC16(sb + B_OFF + off, (const void*)src);
        }
        CP_COMMIT();
        CP_WAIT0();
        __syncthreads();

        float accH[2][2][4];
        #pragma unroll
        for (int mi = 0; mi < 2; mi++)
            #pragma unroll
            for (int ni = 0; ni < 2; ni++)
                #pragma unroll
                for (int q = 0; q < 4; q++) accH[mi][ni][q] = 0.f;

        #pragma unroll
        for (int ks = 0; ks < 4; ks++) {
            uint32_t ah[2][4];
            #pragma unroll
            for (int mi = 0; mi < 2; mi++) {
                const int ar = warp_m * 32 + mi * 16 + i8 + (sub & 1) * 8;
                const int akg = ks * 2 + (sub >> 1);
                const uint32_t off =
                    (uint32_t)(ar * 64 + ((akg ^ (ar & 7)) * 8)) * 2u;
                LDSM_X4(ah[mi][0], ah[mi][1], ah[mi][2], ah[mi][3],
                        sb + A_OFF + off);
            }
            const int nn = warp_n * 16 + i8 + (sub >> 1) * 8;
            const int bkg = ks * 2 + (sub & 1);
            const uint32_t off =
                (uint32_t)(nn * 64 + ((bkg ^ (nn & 7)) * 8)) * 2u;
            uint32_t b0, b1, b2, b3;
            LDSM_X4(b0, b1, b2, b3, sb + B_OFF + off);
            #pragma unroll
            for (int mi = 0; mi < 2; mi++) {
                MMA16816(accH[mi][0], ah[mi], b0, b1);
                MMA16816(accH[mi][1], ah[mi], b2, b3);
            }
        }

        float* ehrp = (float*)(dsm + EHRP_OFF);
        const int g8 = lane >> 2, tg = lane & 3;
        #pragma unroll
        for (int mi = 0; mi < 2; mi++) {
            const int row0 = warp_m * 32 + mi * 16 + g8;
            #pragma unroll
            for (int ni = 0; ni < 2; ni++) {
                const int col = warp_n * 16 + ni * 8 + tg * 2;
                const float b0 = __ldg(be + col), b1 = __ldg(be + col + 1);
                ehrp[row0 * 64 + col]       = fmaxf(accH[mi][ni][0] + b0, 0.f);
                ehrp[row0 * 64 + col + 1]   = fmaxf(accH[mi][ni][1] + b1, 0.f);
                ehrp[(row0 + 8) * 64 + col] = fmaxf(accH[mi][ni][2] + b0, 0.f);
                ehrp[(row0 + 8) * 64 + col + 1] =
                    fmaxf(accH[mi][ni][3] + b1, 0.f);
            }
        }
    }
    __syncthreads();

    // ---- epilogue (warp-per-row, all from smem) ----
    const __half* stash_e = (const __half*)(dsm + STASH_E_OFF);
    const __half* stash_r = (const __half*)(dsm + STASH_R_OFF);
    const float* ehrp     = (const float*)(dsm + EHRP_OFF);
    const float ba0 = ba[0], bf0 = bf2[0];
    float wa[8], wf[8];
    #pragma unroll
    for (int j = 0; j < 8; j++) {
        wa[j] = Wa[lane + 32 * j];
        wf[j] = Wf2[lane + 32 * j];
    }
    const float wfe0 = Wf2[256 + lane], wfe1 = Wf2[256 + lane + 32];

    #pragma unroll 2
    for (int q = 0; q < 8; q++) {
        const int row = wid * 8 + q;
        float e[8], r[8];
        #pragma unroll
        for (int j = 0; j < 8; j++) {
            e[j] = __half2float(stash_e[row * STASH_STRIDE + lane + 32 * j]);
            r[j] = __half2float(stash_r[row * STASH_STRIDE + lane + 32 * j]);
        }
        const float o0 = ehrp[row * 64 + lane];
        const float o1 = ehrp[row * 64 + lane + 32];

        float s = 0.f;
        #pragma unroll
        for (int j = 0; j < 8; j++)
            s = fmaf(tanh_fast(e[j] + r[j]), wa[j], s);
        #pragma unroll
        for (int off = 16; off > 0; off >>= 1)
            s += __shfl_xor_sync(0xffffffffu, s, off);
        const float attn = 1.f / (1.f + __expf(-(s + ba0)));

        float v = o0 * wfe0 + o1 * wfe1;
        #pragma unroll
        for (int j = 0; j < 8; j++) {
            const float f = attn * e[j] + (1.f - attn) * r[j];
            v = fmaf(fmaxf(f, 0.f), wf[j], v);
        }
        #pragma unroll
        for (int off = 16; off > 0; off >>= 1)
            v += __shfl_xor_sync(0xffffffffu, v, off);
        if (lane == 0)
            out[bm * 64 + row] = 1.f / (1.f + __expf(-(v + bf0)));
    }
}

// ============================================================================
extern "C" void kernel_launch(void* const* d_in, const int* in_sizes, int n_in,
                              void* d_out, int out_size) {
    const float* ecc    = (const float*)d_in[0];
    const float* err    = (const float*)d_in[1];
    const float* ehr    = (const float*)d_in[2];
    const float* wt_ecc = (const float*)d_in[3];
    const float* bt_ecc = (const float*)d_in[4];
    const float* wt_err = (const float*)d_in[5];
    const float* bt_err = (const float*)d_in[6];
    const float* W0_ecc = (const float*)d_in[7];
    const float* W1_ecc = (const float*)d_in[8];
    const float* b_ecc  = (const float*)d_in[9];
    const float* W0_err = (const float*)d_in[10];
    const float* W1_err = (const float*)d_in[11];
    const float* b_err  = (const float*)d_in[12];
    const float* Wp_ecc = (const float*)d_in[13];
    const float* bp_ecc = (const float*)d_in[14];
    const float* Wp_err = (const float*)d_in[15];
    const float* bp_err = (const float*)d_in[16];
    const float* Wa     = (const float*)d_in[17];
    const float* ba     = (const float*)d_in[18];
    const float* We     = (const float*)d_in[19];
    const float* be     = (const float*)d_in[20];
    const float* Wf2    = (const float*)d_in[21];
    const float* bf2    = (const float*)d_in[22];

    cudaFuncSetAttribute(fused_kernel,
                         cudaFuncAttributeMaxDynamicSharedMemorySize, FUSED_SMEM);

    precompute<<<745, 256>>>(ecc, err, ehr,
                             wt_ecc, bt_ecc, wt_err, bt_err,
                             W0_ecc, W1_ecc, b_ecc, W0_err, W1_err, b_err,
                             Wp_ecc, bp_ecc, Wp_err, bp_err, We);
    fused_kernel<<<128, 256, FUSED_SMEM>>>(Wa, ba, be, Wf2, bf2,
                                           (float*)d_out);
}